// round 2
// baseline (speedup 1.0000x reference)
#include <cuda_runtime.h>
#include <math.h>

#define B_    8
#define P_    19248
#define C_    81
#define NOBJ_ 8
#define KC_   32
#define PH_   138
#define PW_   138
#define HH_   550
#define WW_   550
#define NPIX_ (PH_*PW_)
#define MTT_  100

// ------------------------- device scratch (static) -------------------------
__device__ double             g_acc[2];          // 0: box-loss raw, 1: conf-loss raw
__device__ double             g_mlsum[B_];       // per-batch mask loss sum (pre-scale)
__device__ unsigned long long g_boxkey[B_][NOBJ_];
__device__ int                g_conf[B_][P_];
__device__ unsigned char      g_pmi[B_][P_];
__device__ float              g_mark[B_][P_];
__device__ int                g_numpos[B_];
__device__ float              g_tmp[B_][NOBJ_][PH_][WW_];  // after y-resize
__device__ unsigned char      g_dm[B_][NPIX_];             // packed gt bits (8 obj / pixel)
__device__ float              g_wts[PH_][9];
__device__ int                g_wi0[PH_];
__device__ int                g_ones[B_][NOBJ_];
__device__ int                g_sel[B_][MTT_];
__device__ int                g_selcnt[B_];

// ------------------------- block reduce helpers -------------------------
__device__ __forceinline__ double blockReduceD(double v) {
    __shared__ double shd[8];
    int ln = threadIdx.x & 31, wd = threadIdx.x >> 5;
    #pragma unroll
    for (int o = 16; o; o >>= 1) v += __shfl_down_sync(0xffffffffu, v, o);
    if (ln == 0) shd[wd] = v;
    __syncthreads();
    v = (threadIdx.x < 8) ? shd[threadIdx.x] : 0.0;
    if (wd == 0) {
        #pragma unroll
        for (int o = 4; o; o >>= 1) v += __shfl_down_sync(0xffffffffu, v, o);
    }
    __syncthreads();
    return v;   // valid on thread 0
}
__device__ __forceinline__ int blockReduceI(int v) {
    __shared__ int shi[8];
    int ln = threadIdx.x & 31, wd = threadIdx.x >> 5;
    #pragma unroll
    for (int o = 16; o; o >>= 1) v += __shfl_down_sync(0xffffffffu, v, o);
    if (ln == 0) shi[wd] = v;
    __syncthreads();
    v = (threadIdx.x < 8) ? shi[threadIdx.x] : 0;
    if (wd == 0) {
        #pragma unroll
        for (int o = 4; o; o >>= 1) v += __shfl_down_sync(0xffffffffu, v, o);
    }
    __syncthreads();
    return v;   // valid on thread 0
}

// ------------------------- K0: init -------------------------
__global__ void k_init() {
    int t = threadIdx.x;
    if (t < PH_) {
        float inv = (float)(1.0 / (138.0 / 550.0));
        float s = ((float)t + 0.5f) * inv - 0.5f;
        int i0 = (int)ceilf(s - inv);
        int i1 = (int)floorf(s + inv);
        if (i0 < 0) i0 = 0;
        if (i1 > HH_ - 1) i1 = HH_ - 1;
        int cnt = i1 - i0 + 1; if (cnt > 9) cnt = 9;
        float w[9]; float wsum = 0.f;
        #pragma unroll
        for (int k = 0; k < 9; k++) {
            float x = __fdiv_rn(fabsf((float)(i0 + k) - s), inv);
            float wv = fmaxf(0.f, 1.f - x);
            if (k >= cnt) wv = 0.f;
            w[k] = wv; wsum += wv;
        }
        #pragma unroll
        for (int k = 0; k < 9; k++) g_wts[t][k] = __fdiv_rn(w[k], wsum);
        g_wi0[t] = i0;
    }
    if (t < B_ * NOBJ_) ((unsigned long long*)g_boxkey)[t] = 0ull;
    if (t < B_) { g_numpos[t] = 0; g_mlsum[t] = 0.0; g_selcnt[t] = 0; }
    if (t < 2) g_acc[t] = 0.0;
}

// ------------------------- K1: matching -------------------------
__global__ void __launch_bounds__(256) k_match(const float* __restrict__ priors,
                                               const float* __restrict__ box_gt,
                                               const int* __restrict__ class_gt) {
    int b = blockIdx.y;
    int p = blockIdx.x * blockDim.x + threadIdx.x;
    __shared__ float sbg[NOBJ_][4];
    if (threadIdx.x < NOBJ_ * 4) ((float*)sbg)[threadIdx.x] = box_gt[b * NOBJ_ * 4 + threadIdx.x];
    __syncthreads();

    unsigned long long keys[NOBJ_];
    if (p < P_) {
        float cx = priors[p*4+0], cy = priors[p*4+1], w = priors[p*4+2], h = priors[p*4+3];
        float w2 = __fmul_rn(w, 0.5f), h2 = __fmul_rn(h, 0.5f);
        float dx1 = __fsub_rn(cx, w2), dy1 = __fsub_rn(cy, h2);
        float dx2 = __fadd_rn(cx, w2), dy2 = __fadd_rn(cy, h2);
        float areaP = __fmul_rn(__fsub_rn(dx2, dx1), __fsub_rn(dy2, dy1));
        float best = -1.f; int besto = 0;
        #pragma unroll
        for (int o = 0; o < NOBJ_; o++) {
            float gx1 = sbg[o][0], gy1 = sbg[o][1], gx2 = sbg[o][2], gy2 = sbg[o][3];
            float ix = fmaxf(__fsub_rn(fminf(gx2, dx2), fmaxf(gx1, dx1)), 0.f);
            float iy = fmaxf(__fsub_rn(fminf(gy2, dy2), fmaxf(gy1, dy1)), 0.f);
            float inter = __fmul_rn(ix, iy);
            float areaG = __fmul_rn(__fsub_rn(gx2, gx1), __fsub_rn(gy2, gy1));
            float iou = __fdiv_rn(inter, __fsub_rn(__fadd_rn(areaG, areaP), inter));
            if (iou > best) { best = iou; besto = o; }
            keys[o] = (((unsigned long long)__float_as_uint(iou)) << 32)
                    | (unsigned long long)(0xFFFFFFFFu - (unsigned)p);
        }
        int cg = class_gt[b * NOBJ_ + besto];
        int cf = cg + 1;
        if (best < 0.5f) cf = -1;
        if (best < 0.4f) cf = 0;
        g_conf[b][p] = cf;
        g_pmi[b][p]  = (unsigned char)besto;
    } else {
        #pragma unroll
        for (int o = 0; o < NOBJ_; o++) keys[o] = 0ull;
    }
    #pragma unroll
    for (int o = 0; o < NOBJ_; o++) {
        unsigned long long kk = keys[o];
        #pragma unroll
        for (int off = 16; off; off >>= 1) {
            unsigned long long other = __shfl_down_sync(0xffffffffu, kk, off);
            if (other > kk) kk = other;
        }
        if ((threadIdx.x & 31) == 0) atomicMax(&g_boxkey[b][o], kk);
    }
}

// ------------------------- K1b: forced matches -------------------------
__global__ void k_override(const int* __restrict__ class_gt) {
    int b = threadIdx.x;
    if (b < B_) {
        for (int o = 0; o < NOBJ_; o++) {
            unsigned long long k = g_boxkey[b][o];
            unsigned p = 0xFFFFFFFFu - (unsigned)(k & 0xFFFFFFFFull);
            g_conf[b][p] = class_gt[b * NOBJ_ + o] + 1;
            g_pmi[b][p]  = (unsigned char)o;
        }
    }
}

// ------------------------- K2: per-prior lse/mark/nll + pos losses -------------------------
__global__ void __launch_bounds__(256) k_class(const float* __restrict__ class_p,
                                               const float* __restrict__ box_p,
                                               const float* __restrict__ priors,
                                               const float* __restrict__ box_gt) {
    int gw = (blockIdx.x * blockDim.x + threadIdx.x) >> 5;
    int lane = threadIdx.x & 31;
    if (gw >= B_ * P_) return;
    int b = gw / P_, p = gw % P_;
    const float* xp = class_p + (size_t)gw * C_;
    float v0 = xp[lane];
    float v1 = xp[lane + 32];
    float v2 = (lane < C_ - 64) ? xp[lane + 64] : 0.f;
    float m = fmaxf(v0, v1);
    if (lane < C_ - 64) m = fmaxf(m, v2);
    #pragma unroll
    for (int off = 16; off; off >>= 1) m = fmaxf(m, __shfl_xor_sync(0xffffffffu, m, off));
    float s = expf(v0 - m) + expf(v1 - m);
    if (lane < C_ - 64) s += expf(v2 - m);
    #pragma unroll
    for (int off = 16; off; off >>= 1) s += __shfl_xor_sync(0xffffffffu, s, off);
    float lse = m + logf(s);

    int cf = g_conf[b][p];
    int tgt = cf > 0 ? cf : 0;
    float cand = (tgt < 32) ? v0 : ((tgt < 64) ? v1 : v2);
    float xt = __shfl_sync(0xffffffffu, cand, tgt & 31);
    float x0 = __shfl_sync(0xffffffffu, v0, 0);

    if (lane == 0) {
        bool pos = cf > 0;
        g_mark[b][p] = (pos || cf < 0) ? 0.f : (lse - x0);
        if (pos) {
            atomicAdd(&g_numpos[b], 1);
            int o = g_pmi[b][p];
            const float* bg = box_gt + (size_t)(b * NOBJ_ + o) * 4;
            float mnx = bg[0], mny = bg[1], mxx = bg[2], mxy = bg[3];
            const float* pr = priors + (size_t)p * 4;
            float pcx = pr[0], pcy = pr[1], pw = pr[2], phh = pr[3];
            float off0 = __fdiv_rn(__fsub_rn(__fmul_rn(__fadd_rn(mnx, mxx), 0.5f), pcx), __fmul_rn(0.1f, pw));
            float off1 = __fdiv_rn(__fsub_rn(__fmul_rn(__fadd_rn(mny, mxy), 0.5f), pcy), __fmul_rn(0.1f, phh));
            float off2 = __fdiv_rn(logf(__fdiv_rn(__fsub_rn(mxx, mnx), pw)), 0.2f);
            float off3 = __fdiv_rn(logf(__fdiv_rn(__fsub_rn(mxy, mny), phh)), 0.2f);
            const float* bp = box_p + (size_t)gw * 4;
            float lb = 0.f, d;
            d = fabsf(bp[0] - off0); lb += (d < 1.f) ? 0.5f*d*d : d - 0.5f;
            d = fabsf(bp[1] - off1); lb += (d < 1.f) ? 0.5f*d*d : d - 0.5f;
            d = fabsf(bp[2] - off2); lb += (d < 1.f) ? 0.5f*d*d : d - 0.5f;
            d = fabsf(bp[3] - off3); lb += (d < 1.f) ? 0.5f*d*d : d - 0.5f;
            atomicAdd(&g_acc[0], (double)lb);
            atomicAdd(&g_acc[1], (double)(lse - xt));   // positive nll
        }
    }
}

// ------------------------- K3: hard-negative select via radix -------------------------
__global__ void __launch_bounds__(256) k_select() {
    int b = blockIdx.x;
    int tid = threadIdx.x;
    __shared__ int hist[256];
    __shared__ unsigned sh_prefix;
    __shared__ int sh_rem;
    __shared__ int sh_ceq;
    __shared__ int sh_taken;
    __shared__ int sh_wcnt[8];

    int np = g_numpos[b];
    long long kll = 3LL * np; if (kll > P_ - 1) kll = P_ - 1;
    if (kll <= 0) return;
    if (tid == 0) { sh_prefix = 0u; sh_rem = (int)kll; }
    __syncthreads();
    const float* mk = &g_mark[b][0];

    for (int pass = 0; pass < 4; pass++) {
        int shift = 24 - 8 * pass;
        unsigned himask = (pass == 0) ? 0u : (0xFFFFFFFFu << (shift + 8));
        hist[tid] = 0;
        __syncthreads();
        unsigned pref = sh_prefix;
        for (int p = tid; p < P_; p += 256) {
            unsigned u = __float_as_uint(mk[p]);
            if ((u & himask) == pref)
                atomicAdd(&hist[(u >> shift) & 255], 1);
        }
        __syncthreads();
        if (tid == 0) {
            int rem = sh_rem;
            int cum = 0, bin = 255;
            for (; bin > 0; bin--) {
                cum += hist[bin];
                if (cum >= rem) break;
            }
            if (cum < rem) cum += hist[0];   // bin==0 fallthrough
            sh_rem = rem - (cum - hist[bin]);
            sh_prefix = pref | ((unsigned)bin << shift);
        }
        __syncthreads();
    }
    unsigned tb = sh_prefix;
    int quota = sh_rem;

    double sgt = 0.0, seq = 0.0; int ceq = 0;
    for (int p = tid; p < P_; p += 256) {
        float v = mk[p];
        unsigned u = __float_as_uint(v);
        if (u > tb) sgt += (double)v;
        else if (u == tb) { seq += (double)v; ceq++; }
    }
    double sgt_t = blockReduceD(sgt);
    double seq_t = blockReduceD(seq);
    int    ceq_t = blockReduceI(ceq);
    if (tid == 0) sh_ceq = ceq_t;
    __syncthreads();
    bool ordered = (sh_ceq != quota) && (tb != 0u);
    if (tid == 0) atomicAdd(&g_acc[1], sgt_t + (ordered ? 0.0 : seq_t));

    if (ordered) {
        if (tid == 0) sh_taken = 0;
        __syncthreads();
        double sord = 0.0;
        for (int base = 0; base < P_; base += 256) {
            int p = base + tid;
            bool pred = (p < P_) && (__float_as_uint(mk[p]) == tb);
            unsigned bal = __ballot_sync(0xffffffffu, pred);
            int wd = tid >> 5, ln = tid & 31;
            if (ln == 0) sh_wcnt[wd] = __popc(bal);
            __syncthreads();
            int wbase = 0;
            for (int w = 0; w < wd; w++) wbase += sh_wcnt[w];
            int rank = sh_taken + wbase + __popc(bal & ((1u << ln) - 1u));
            if (pred && rank < quota) sord += (double)mk[p];
            __syncthreads();
            if (tid == 0) {
                int tot = 0;
                for (int w = 0; w < 8; w++) tot += sh_wcnt[w];
                sh_taken += tot;
            }
            __syncthreads();
            if (sh_taken >= quota) break;
        }
        double st = blockReduceD(sord);
        if (tid == 0) atomicAdd(&g_acc[1], st);
    }
}

// ------------------------- K4a: resize y (550->138) -------------------------
__global__ void __launch_bounds__(128) k_resize_y(const float* __restrict__ mg) {
    int id = blockIdx.x;
    int yo = id % PH_; id /= PH_;
    int o  = id % NOBJ_;
    int b  = id / NOBJ_;
    int i0 = g_wi0[yo];
    float w[9];
    #pragma unroll
    for (int t = 0; t < 9; t++) w[t] = g_wts[yo][t];
    const float* src = mg + ((size_t)(b * NOBJ_ + o)) * HH_ * WW_;
    const float* rows[9];
    #pragma unroll
    for (int t = 0; t < 9; t++) {
        int yi = i0 + t; if (yi > HH_ - 1) yi = HH_ - 1;
        rows[t] = src + (size_t)yi * WW_;
    }
    float* dst = &g_tmp[b][o][yo][0];
    for (int x = threadIdx.x; x < WW_; x += 128) {
        float s = 0.f;
        #pragma unroll
        for (int t = 0; t < 9; t++) s += w[t] * rows[t][x];
        dst[x] = s;
    }
}

// ------------------------- K4b: resize x + threshold + pack -------------------------
__global__ void __launch_bounds__(256) k_resize_x() {
    int b  = blockIdx.y;
    int px = blockIdx.x * blockDim.x + threadIdx.x;
    if (px >= NPIX_) return;
    int yo = px / PW_, xo = px % PW_;
    int i0 = g_wi0[xo];
    float w[9];
    #pragma unroll
    for (int t = 0; t < 9; t++) w[t] = g_wts[xo][t];
    unsigned bits = 0;
    #pragma unroll
    for (int o = 0; o < NOBJ_; o++) {
        const float* row = &g_tmp[b][o][yo][0];
        float s = 0.f;
        #pragma unroll
        for (int t = 0; t < 9; t++) {
            int xi = i0 + t; if (xi > WW_ - 1) xi = WW_ - 1;
            s += w[t] * row[xi];
        }
        if (s > 0.5f) bits |= (1u << o);
    }
    g_dm[b][px] = (unsigned char)bits;
}

// ------------------------- K5: total ones per (b,o) -------------------------
__global__ void __launch_bounds__(256) k_count_ones() {
    int b = blockIdx.x;
    int cnt[NOBJ_];
    #pragma unroll
    for (int o = 0; o < NOBJ_; o++) cnt[o] = 0;
    for (int px = threadIdx.x; px < NPIX_; px += 256) {
        unsigned v = g_dm[b][px];
        #pragma unroll
        for (int o = 0; o < NOBJ_; o++) cnt[o] += (v >> o) & 1;
    }
    __shared__ int sh[NOBJ_];
    if (threadIdx.x < NOBJ_) sh[threadIdx.x] = 0;
    __syncthreads();
    #pragma unroll
    for (int o = 0; o < NOBJ_; o++) atomicAdd(&sh[o], cnt[o]);
    __syncthreads();
    if (threadIdx.x < NOBJ_) g_ones[b][threadIdx.x] = sh[threadIdx.x];
}

// ------------------------- K6: pick first min(numpos,100) positives -------------------------
__global__ void __launch_bounds__(256) k_pick() {
    int b = blockIdx.x;
    int tid = threadIdx.x;
    int np = g_numpos[b];
    int cap = np < MTT_ ? np : MTT_;
    __shared__ int sh_taken;
    __shared__ int sh_wcnt[8];
    if (tid == 0) { sh_taken = 0; g_selcnt[b] = cap; }
    __syncthreads();
    if (cap == 0) return;
    for (int base = 0; base < P_; base += 256) {
        int p = base + tid;
        bool pred = (p < P_) && (g_conf[b][p] > 0);
        unsigned bal = __ballot_sync(0xffffffffu, pred);
        int wd = tid >> 5, ln = tid & 31;
        if (ln == 0) sh_wcnt[wd] = __popc(bal);
        __syncthreads();
        int wbase = 0;
        for (int w = 0; w < wd; w++) wbase += sh_wcnt[w];
        int rank = sh_taken + wbase + __popc(bal & ((1u << ln) - 1u));
        if (pred && rank < cap) g_sel[b][rank] = p;
        __syncthreads();
        if (tid == 0) {
            int tot = 0;
            for (int w = 0; w < 8; w++) tot += sh_wcnt[w];
            sh_taken += tot;
        }
        __syncthreads();
        if (sh_taken >= cap) break;
    }
}

// ------------------------- K7: mask BCE -------------------------
__global__ void __launch_bounds__(256) k_mask(const float* __restrict__ proto_p,
                                              const float* __restrict__ coef_p,
                                              const float* __restrict__ box_gt) {
    int b = blockIdx.y, k = blockIdx.x;
    if (k >= g_selcnt[b]) return;
    int p = g_sel[b][k];
    int o = g_pmi[b][p];
    __shared__ float sc[KC_];
    __shared__ float sbox[4];
    if (threadIdx.x < KC_) sc[threadIdx.x] = coef_p[((size_t)(b * P_ + p)) * KC_ + threadIdx.x];
    if (threadIdx.x >= 32 && threadIdx.x < 36)
        sbox[threadIdx.x - 32] = box_gt[(size_t)(b * NOBJ_ + o) * 4 + (threadIdx.x - 32)];
    __syncthreads();
    float bx1 = sbox[0], by1 = sbox[1], bx2 = sbox[2], by2 = sbox[3];

    float ax = bx1 * 138.f, bx = bx2 * 138.f;
    float x1 = fminf(ax, bx), x2 = fmaxf(ax, bx);
    x1 = fmaxf(x1 - 1.f, 0.f); x2 = fminf(x2 + 1.f, 138.f);
    float ay = by1 * 138.f, by = by2 * 138.f;
    float y1 = fminf(ay, by), y2 = fmaxf(ay, by);
    y1 = fmaxf(y1 - 1.f, 0.f); y2 = fminf(y2 + 1.f, 138.f);
    int xlo = (int)ceilf(x1), xhi = (int)ceilf(x2);
    int ylo = (int)ceilf(y1), yhi = (int)ceilf(y2);
    if (xlo < 0) xlo = 0; if (xhi > PW_) xhi = PW_;
    if (ylo < 0) ylo = 0; if (yhi > PH_) yhi = PH_;
    int rw = xhi - xlo, rh = yhi - ylo;
    if (rw < 0) rw = 0; if (rh < 0) rh = 0;
    int rectN = rw * rh;

    const float L = 16.118095651f;
    double zsum = 0.0; int onesIn = 0;
    for (int i = threadIdx.x; i < rectN; i += 256) {
        int y = ylo + i / rw;
        int x = xlo + i % rw;
        const float4* pr = (const float4*)(proto_p + (((size_t)b * PH_ + y) * PW_ + x) * KC_);
        float z = 0.f;
        #pragma unroll
        for (int q = 0; q < 8; q++) {
            float4 v = pr[q];
            z += v.x * sc[4*q] + v.y * sc[4*q+1] + v.z * sc[4*q+2] + v.w * sc[4*q+3];
        }
        int gt = (g_dm[b][y * PW_ + x] >> o) & 1;
        float zc = fminf(fmaxf(z, -L), L);
        float sp = fmaxf(zc, 0.f) + __logf(1.f + __expf(-fabsf(zc)));
        zsum += (double)(sp - (gt ? zc : 0.f));
        onesIn += gt;
    }
    double zt = blockReduceD(zsum);
    int    ot = blockReduceI(onesIn);
    if (threadIdx.x == 0) {
        float A  = -logf(1e-7f);        // bce for gt=1 outside crop (p clipped to 1e-7)
        float BT = -log1pf(-1e-7f);     // bce for gt=0 outside crop
        int onesTot  = g_ones[b][o];
        int onesOut  = onesTot - ot;
        int zerosOut = (NPIX_ - rectN) - onesOut;
        double bce = zt + (double)onesOut * (double)A + (double)zerosOut * (double)BT;
        float denom = (bx2 - bx1) * (by2 - by1);
        atomicAdd(&g_mlsum[b], bce / (double)denom);
    }
}

// ------------------------- K8: final combine -------------------------
__global__ void k_final(float* out) {
    if (threadIdx.x == 0) {
        double lm = 0.0;
        for (int b = 0; b < B_; b++) {
            double s = 1.0;
            int np = g_numpos[b];
            if (np > MTT_) {
                float npf = (float)np;
                float nposf = fminf(npf, (float)MTT_);
                s = (double)(npf / fmaxf(nposf, 1.f));
            }
            lm += g_mlsum[b] * s;
        }
        double total = 1.5 * g_acc[0] + g_acc[1] + lm * 6.125 / 138.0 / 138.0;
        out[0] = (float)total;
    }
}

// ------------------------- launch -------------------------
extern "C" void kernel_launch(void* const* d_in, const int* in_sizes, int n_in,
                              void* d_out, int out_size) {
    const float* class_p  = (const float*)d_in[0];
    const float* box_p    = (const float*)d_in[1];
    const float* coef_p   = (const float*)d_in[2];
    const float* proto_p  = (const float*)d_in[3];
    const float* priors   = (const float*)d_in[4];
    const float* box_gt   = (const float*)d_in[5];
    const float* mask_gt  = (const float*)d_in[6];
    const int*   class_gt = (const int*)d_in[7];
    float* out = (float*)d_out;

    k_init<<<1, 256>>>();
    dim3 gm((P_ + 255) / 256, B_);
    k_match<<<gm, 256>>>(priors, box_gt, class_gt);
    k_override<<<1, 32>>>(class_gt);
    k_class<<<(B_ * P_) / 8, 256>>>(class_p, box_p, priors, box_gt);
    k_select<<<B_, 256>>>();
    k_resize_y<<<B_ * NOBJ_ * PH_, 128>>>(mask_gt);
    dim3 gx((NPIX_ + 255) / 256, B_);
    k_resize_x<<<gx, 256>>>();
    k_count_ones<<<B_, 256>>>();
    k_pick<<<B_, 256>>>();
    dim3 gk(MTT_, B_);
    k_mask<<<gk, 256>>>(proto_p, coef_p, box_gt);
    k_final<<<1, 32>>>(out);
}

// round 3
// speedup vs baseline: 1.1081x; 1.1081x over previous
#include <cuda_runtime.h>
#include <math.h>

#define B_    8
#define P_    19248
#define C_    81
#define NOBJ_ 8
#define KC_   32
#define PH_   138
#define PW_   138
#define HH_   550
#define WW_   550
#define NPIX_ (PH_*PW_)
#define MTT_  100

#define MATCH_BLOCKS   608          // 76 blocks/batch * 8
#define RESY_BLOCKS    (B_*NOBJ_*PH_)   // 8832
#define CLASS_BLOCKS   19248        // B_*P_ warps / 8
#define RESX_PERB      75           // 75*256 >= 19044
#define RESX_BLOCKS    (B_*RESX_PERB)
#define SEG3           38           // ceil(P_/512)

// ------------------------- device scratch (static) -------------------------
__device__ double             g_acc[2];          // 0: box-loss raw, 1: conf-loss raw
__device__ double             g_mlsum[B_];
__device__ unsigned long long g_boxkey[B_][NOBJ_];
__device__ int                g_conf[B_][P_];
__device__ unsigned char      g_pmi[B_][P_];
__device__ float              g_mark[B_][P_];
__device__ int                g_numpos[B_];
__device__ float              g_tmp[B_][NOBJ_][PH_][WW_];
__device__ unsigned char      g_dm[B_][NPIX_];
__device__ float              g_wts[PH_][9];
__device__ int                g_wi0[PH_];
__device__ int                g_ones[B_][NOBJ_];
__device__ int                g_sel[B_][MTT_];
__device__ int                g_selcnt[B_];

// ------------------------- reduce / scan helpers -------------------------
// 256-thread block reduce (broadcast result to all threads)
__device__ __forceinline__ double bRedD256(double v) {
    __shared__ double sd[8];
    int ln = threadIdx.x & 31, wd = threadIdx.x >> 5;
    #pragma unroll
    for (int o = 16; o; o >>= 1) v += __shfl_down_sync(0xffffffffu, v, o);
    if (ln == 0) sd[wd] = v;
    __syncthreads();
    v = (threadIdx.x < 8) ? sd[threadIdx.x] : 0.0;
    if (wd == 0) {
        #pragma unroll
        for (int o = 4; o; o >>= 1) v += __shfl_down_sync(0xffffffffu, v, o);
        if (ln == 0) sd[0] = v;
    }
    __syncthreads();
    double r = sd[0];
    __syncthreads();
    return r;
}
__device__ __forceinline__ int bRedI256(int v) {
    __shared__ int si[8];
    int ln = threadIdx.x & 31, wd = threadIdx.x >> 5;
    #pragma unroll
    for (int o = 16; o; o >>= 1) v += __shfl_down_sync(0xffffffffu, v, o);
    if (ln == 0) si[wd] = v;
    __syncthreads();
    v = (threadIdx.x < 8) ? si[threadIdx.x] : 0;
    if (wd == 0) {
        #pragma unroll
        for (int o = 4; o; o >>= 1) v += __shfl_down_sync(0xffffffffu, v, o);
        if (ln == 0) si[0] = v;
    }
    __syncthreads();
    int r = si[0];
    __syncthreads();
    return r;
}
// 512-thread versions
__device__ __forceinline__ double bRedD512(double v) {
    __shared__ double sd[16];
    int ln = threadIdx.x & 31, wd = threadIdx.x >> 5;
    #pragma unroll
    for (int o = 16; o; o >>= 1) v += __shfl_down_sync(0xffffffffu, v, o);
    if (ln == 0) sd[wd] = v;
    __syncthreads();
    v = (threadIdx.x < 16) ? sd[threadIdx.x] : 0.0;
    if (wd == 0) {
        #pragma unroll
        for (int o = 8; o; o >>= 1) v += __shfl_down_sync(0xffffffffu, v, o);
        if (ln == 0) sd[0] = v;
    }
    __syncthreads();
    double r = sd[0];
    __syncthreads();
    return r;
}
__device__ __forceinline__ int bRedI512(int v) {
    __shared__ int si[16];
    int ln = threadIdx.x & 31, wd = threadIdx.x >> 5;
    #pragma unroll
    for (int o = 16; o; o >>= 1) v += __shfl_down_sync(0xffffffffu, v, o);
    if (ln == 0) si[wd] = v;
    __syncthreads();
    v = (threadIdx.x < 16) ? si[threadIdx.x] : 0;
    if (wd == 0) {
        #pragma unroll
        for (int o = 8; o; o >>= 1) v += __shfl_down_sync(0xffffffffu, v, o);
        if (ln == 0) si[0] = v;
    }
    __syncthreads();
    int r = si[0];
    __syncthreads();
    return r;
}
// 512-thread exclusive scan
__device__ __forceinline__ int bScanEx512(int v, int* sh) {
    int tid = threadIdx.x;
    sh[tid] = v;
    __syncthreads();
    #pragma unroll
    for (int off = 1; off < 512; off <<= 1) {
        int t = (tid >= off) ? sh[tid - off] : 0;
        __syncthreads();
        sh[tid] += t;
        __syncthreads();
    }
    int incl = sh[tid];
    __syncthreads();
    return incl - v;
}

// ------------------------- K0: init -------------------------
__global__ void k_init() {
    int t = threadIdx.x;
    if (t < PH_) {
        float inv = (float)(1.0 / (138.0 / 550.0));
        float s = ((float)t + 0.5f) * inv - 0.5f;
        int i0 = (int)ceilf(s - inv);
        int i1 = (int)floorf(s + inv);
        if (i0 < 0) i0 = 0;
        if (i1 > HH_ - 1) i1 = HH_ - 1;
        int cnt = i1 - i0 + 1; if (cnt > 9) cnt = 9;
        float w[9]; float wsum = 0.f;
        #pragma unroll
        for (int k = 0; k < 9; k++) {
            float x = __fdiv_rn(fabsf((float)(i0 + k) - s), inv);
            float wv = fmaxf(0.f, 1.f - x);
            if (k >= cnt) wv = 0.f;
            w[k] = wv; wsum += wv;
        }
        #pragma unroll
        for (int k = 0; k < 9; k++) g_wts[t][k] = __fdiv_rn(w[k], wsum);
        g_wi0[t] = i0;
    }
    if (t < B_ * NOBJ_) {
        ((unsigned long long*)g_boxkey)[t] = 0ull;
        ((int*)g_ones)[t] = 0;
    }
    if (t < B_) { g_numpos[t] = 0; g_mlsum[t] = 0.0; g_selcnt[t] = 0; }
    if (t < 2) g_acc[t] = 0.0;
}

// ------------------------- MEGA1: match + resize_y -------------------------
__global__ void __launch_bounds__(256) mega1(const float* __restrict__ priors,
                                             const float* __restrict__ box_gt,
                                             const int* __restrict__ class_gt,
                                             const float* __restrict__ mg) {
    if (blockIdx.x < MATCH_BLOCKS) {
        // ---- matching role ----
        int blk = blockIdx.x;
        int b = blk / 76;
        int p = (blk % 76) * 256 + threadIdx.x;
        __shared__ float sbg[NOBJ_][4];
        if (threadIdx.x < NOBJ_ * 4) ((float*)sbg)[threadIdx.x] = box_gt[b * NOBJ_ * 4 + threadIdx.x];
        __syncthreads();

        unsigned long long keys[NOBJ_];
        if (p < P_) {
            float cx = priors[p*4+0], cy = priors[p*4+1], w = priors[p*4+2], h = priors[p*4+3];
            float w2 = __fmul_rn(w, 0.5f), h2 = __fmul_rn(h, 0.5f);
            float dx1 = __fsub_rn(cx, w2), dy1 = __fsub_rn(cy, h2);
            float dx2 = __fadd_rn(cx, w2), dy2 = __fadd_rn(cy, h2);
            float areaP = __fmul_rn(__fsub_rn(dx2, dx1), __fsub_rn(dy2, dy1));
            float best = -1.f; int besto = 0;
            #pragma unroll
            for (int o = 0; o < NOBJ_; o++) {
                float gx1 = sbg[o][0], gy1 = sbg[o][1], gx2 = sbg[o][2], gy2 = sbg[o][3];
                float ix = fmaxf(__fsub_rn(fminf(gx2, dx2), fmaxf(gx1, dx1)), 0.f);
                float iy = fmaxf(__fsub_rn(fminf(gy2, dy2), fmaxf(gy1, dy1)), 0.f);
                float inter = __fmul_rn(ix, iy);
                float areaG = __fmul_rn(__fsub_rn(gx2, gx1), __fsub_rn(gy2, gy1));
                float iou = __fdiv_rn(inter, __fsub_rn(__fadd_rn(areaG, areaP), inter));
                if (iou > best) { best = iou; besto = o; }
                keys[o] = (((unsigned long long)__float_as_uint(iou)) << 32)
                        | (unsigned long long)(0xFFFFFFFFu - (unsigned)p);
            }
            int cg = class_gt[b * NOBJ_ + besto];
            int cf = cg + 1;
            if (best < 0.5f) cf = -1;
            if (best < 0.4f) cf = 0;
            g_conf[b][p] = cf;
            g_pmi[b][p]  = (unsigned char)besto;
        } else {
            #pragma unroll
            for (int o = 0; o < NOBJ_; o++) keys[o] = 0ull;
        }
        #pragma unroll
        for (int o = 0; o < NOBJ_; o++) {
            unsigned long long kk = keys[o];
            #pragma unroll
            for (int off = 16; off; off >>= 1) {
                unsigned long long other = __shfl_down_sync(0xffffffffu, kk, off);
                if (other > kk) kk = other;
            }
            if ((threadIdx.x & 31) == 0) atomicMax(&g_boxkey[b][o], kk);
        }
    } else {
        // ---- resize_y role ----
        int id = blockIdx.x - MATCH_BLOCKS;
        int yo = id % PH_; id /= PH_;
        int o  = id % NOBJ_;
        int b  = id / NOBJ_;
        int i0 = g_wi0[yo];
        float w[9];
        #pragma unroll
        for (int t = 0; t < 9; t++) w[t] = g_wts[yo][t];
        const float* src = mg + ((size_t)(b * NOBJ_ + o)) * HH_ * WW_;
        const float* rows[9];
        #pragma unroll
        for (int t = 0; t < 9; t++) {
            int yi = i0 + t; if (yi > HH_ - 1) yi = HH_ - 1;
            rows[t] = src + (size_t)yi * WW_;
        }
        float* dst = &g_tmp[b][o][yo][0];
        for (int x = threadIdx.x; x < WW_; x += 256) {
            float s = 0.f;
            #pragma unroll
            for (int t = 0; t < 9; t++) s += w[t] * rows[t][x];
            dst[x] = s;
        }
    }
}

// ------------------------- K1b: forced matches -------------------------
__global__ void k_override(const int* __restrict__ class_gt) {
    int b = threadIdx.x;
    if (b < B_) {
        for (int o = 0; o < NOBJ_; o++) {
            unsigned long long k = g_boxkey[b][o];
            unsigned p = 0xFFFFFFFFu - (unsigned)(k & 0xFFFFFFFFull);
            g_conf[b][p] = class_gt[b * NOBJ_ + o] + 1;
            g_pmi[b][p]  = (unsigned char)o;
        }
    }
}

// ------------------------- MEGA2: class + resize_x(+ones) -------------------------
__global__ void __launch_bounds__(256) mega2(const float* __restrict__ class_p,
                                             const float* __restrict__ box_p,
                                             const float* __restrict__ priors,
                                             const float* __restrict__ box_gt) {
    if (blockIdx.x < CLASS_BLOCKS) {
        // ---- class role: 1 warp per prior ----
        int gw = blockIdx.x * 8 + (threadIdx.x >> 5);
        int lane = threadIdx.x & 31;
        int b = gw / P_, p = gw % P_;
        const float* xp = class_p + (size_t)gw * C_;
        float v0 = xp[lane];
        float v1 = xp[lane + 32];
        float v2 = (lane < C_ - 64) ? xp[lane + 64] : 0.f;
        float m = fmaxf(v0, v1);
        if (lane < C_ - 64) m = fmaxf(m, v2);
        #pragma unroll
        for (int off = 16; off; off >>= 1) m = fmaxf(m, __shfl_xor_sync(0xffffffffu, m, off));
        float s = __expf(v0 - m) + __expf(v1 - m);
        if (lane < C_ - 64) s += __expf(v2 - m);
        #pragma unroll
        for (int off = 16; off; off >>= 1) s += __shfl_xor_sync(0xffffffffu, s, off);
        float lse = m + __logf(s);

        int cf = g_conf[b][p];
        int tgt = cf > 0 ? cf : 0;
        float cand = (tgt < 32) ? v0 : ((tgt < 64) ? v1 : v2);
        float xt = __shfl_sync(0xffffffffu, cand, tgt & 31);
        float x0 = __shfl_sync(0xffffffffu, v0, 0);

        if (lane == 0) {
            bool pos = cf > 0;
            g_mark[b][p] = (pos || cf < 0) ? 0.f : (lse - x0);
            if (pos) {
                atomicAdd(&g_numpos[b], 1);
                int o = g_pmi[b][p];
                const float* bg = box_gt + (size_t)(b * NOBJ_ + o) * 4;
                float mnx = bg[0], mny = bg[1], mxx = bg[2], mxy = bg[3];
                const float* pr = priors + (size_t)p * 4;
                float pcx = pr[0], pcy = pr[1], pw = pr[2], phh = pr[3];
                float off0 = __fdiv_rn(__fsub_rn(__fmul_rn(__fadd_rn(mnx, mxx), 0.5f), pcx), __fmul_rn(0.1f, pw));
                float off1 = __fdiv_rn(__fsub_rn(__fmul_rn(__fadd_rn(mny, mxy), 0.5f), pcy), __fmul_rn(0.1f, phh));
                float off2 = __fdiv_rn(logf(__fdiv_rn(__fsub_rn(mxx, mnx), pw)), 0.2f);
                float off3 = __fdiv_rn(logf(__fdiv_rn(__fsub_rn(mxy, mny), phh)), 0.2f);
                const float* bp = box_p + (size_t)gw * 4;
                float lb = 0.f, d;
                d = fabsf(bp[0] - off0); lb += (d < 1.f) ? 0.5f*d*d : d - 0.5f;
                d = fabsf(bp[1] - off1); lb += (d < 1.f) ? 0.5f*d*d : d - 0.5f;
                d = fabsf(bp[2] - off2); lb += (d < 1.f) ? 0.5f*d*d : d - 0.5f;
                d = fabsf(bp[3] - off3); lb += (d < 1.f) ? 0.5f*d*d : d - 0.5f;
                atomicAdd(&g_acc[0], (double)lb);
                atomicAdd(&g_acc[1], (double)(lse - xt));
            }
        }
    } else {
        // ---- resize_x + per-(b,o) ones count ----
        int id = blockIdx.x - CLASS_BLOCKS;
        int b  = id / RESX_PERB;
        int px = (id % RESX_PERB) * 256 + threadIdx.x;
        unsigned bits = 0;
        if (px < NPIX_) {
            int yo = px / PW_, xo = px % PW_;
            int i0 = g_wi0[xo];
            float w[9];
            #pragma unroll
            for (int t = 0; t < 9; t++) w[t] = g_wts[xo][t];
            #pragma unroll
            for (int o = 0; o < NOBJ_; o++) {
                const float* row = &g_tmp[b][o][yo][0];
                float s = 0.f;
                #pragma unroll
                for (int t = 0; t < 9; t++) {
                    int xi = i0 + t; if (xi > WW_ - 1) xi = WW_ - 1;
                    s += w[t] * row[xi];
                }
                if (s > 0.5f) bits |= (1u << o);
            }
            g_dm[b][px] = (unsigned char)bits;
        }
        __shared__ int shc[NOBJ_];
        if (threadIdx.x < NOBJ_) shc[threadIdx.x] = 0;
        __syncthreads();
        int lane = threadIdx.x & 31;
        #pragma unroll
        for (int o = 0; o < NOBJ_; o++) {
            unsigned mb = __ballot_sync(0xffffffffu, (bits >> o) & 1);
            if (lane == 0 && mb) atomicAdd(&shc[o], __popc(mb));
        }
        __syncthreads();
        if (threadIdx.x < NOBJ_ && shc[threadIdx.x]) atomicAdd(&g_ones[b][threadIdx.x], shc[threadIdx.x]);
    }
}

// ------------------------- MEGA3: select (8 blocks) + pick (8 blocks) -------------------------
__global__ void __launch_bounds__(512) mega3() {
    extern __shared__ float smk[];          // P_ floats (select role)
    __shared__ int hist[256];
    __shared__ int sscan[512];
    __shared__ unsigned sh_prefix;
    __shared__ int sh_rem;
    int tid = threadIdx.x;

    if (blockIdx.x < 8) {
        // ---------------- select role ----------------
        int b = blockIdx.x;
        int np = g_numpos[b];
        long long kll = 3LL * np; if (kll > P_ - 1) kll = P_ - 1;
        if (kll <= 0) return;
        for (int p = tid; p < P_; p += 512) smk[p] = g_mark[b][p];
        if (tid == 0) { sh_prefix = 0u; sh_rem = (int)kll; }
        __syncthreads();

        for (int pass = 0; pass < 4; pass++) {
            int shift = 24 - 8 * pass;
            unsigned himask = (pass == 0) ? 0u : (0xFFFFFFFFu << (shift + 8));
            if (tid < 256) hist[tid] = 0;
            __syncthreads();
            unsigned pref = sh_prefix;
            for (int p = tid; p < P_; p += 512) {
                unsigned u = __float_as_uint(smk[p]);
                if ((u & himask) == pref)
                    atomicAdd(&hist[(u >> shift) & 255], 1);
            }
            __syncthreads();
            if (tid == 0) {
                int rem = sh_rem;
                int cum = 0, bin = 255;
                for (; bin > 0; bin--) {
                    cum += hist[bin];
                    if (cum >= rem) break;
                }
                if (cum < rem) cum += hist[0];   // landed in bin 0
                sh_rem = rem - (cum - hist[bin]);
                sh_prefix = pref | ((unsigned)bin << shift);
            }
            __syncthreads();
        }
        unsigned tb = sh_prefix;
        int quota = sh_rem;

        double sgt = 0.0, seq = 0.0; int ceq = 0;
        for (int p = tid; p < P_; p += 512) {
            float v = smk[p];
            unsigned u = __float_as_uint(v);
            if (u > tb) sgt += (double)v;
            else if (u == tb) { seq += (double)v; ceq++; }
        }
        double sgt_t = bRedD512(sgt);
        double seq_t = bRedD512(seq);
        int    ceq_t = bRedI512(ceq);
        bool ordered = (ceq_t != quota) && (tb != 0u);
        if (tid == 0) atomicAdd(&g_acc[1], sgt_t + (ordered ? 0.0 : seq_t));

        if (ordered) {
            int s0 = tid * SEG3, s1 = s0 + SEG3; if (s1 > P_) s1 = P_;
            int c = 0;
            for (int p = s0; p < s1; p++)
                if (__float_as_uint(smk[p]) == tb) c++;
            int pre = bScanEx512(c, sscan);
            double sord = 0.0; int r = pre;
            for (int p = s0; p < s1; p++) {
                if (__float_as_uint(smk[p]) == tb) {
                    if (r < quota) sord += (double)smk[p];
                    r++;
                }
            }
            double st = bRedD512(sord);
            if (tid == 0) atomicAdd(&g_acc[1], st);
        }
    } else {
        // ---------------- pick role ----------------
        int b = blockIdx.x - 8;
        int np = g_numpos[b];
        int cap = np < MTT_ ? np : MTT_;
        if (tid == 0) g_selcnt[b] = cap;
        int s0 = tid * SEG3, s1 = s0 + SEG3; if (s1 > P_) s1 = P_;
        int c = 0;
        for (int p = s0; p < s1; p++)
            if (g_conf[b][p] > 0) c++;
        int pre = bScanEx512(c, sscan);
        int r = pre;
        for (int p = s0; p < s1; p++) {
            if (g_conf[b][p] > 0) {
                if (r < cap) g_sel[b][r] = p;
                r++;
            }
        }
    }
}

// ------------------------- K7: mask BCE -------------------------
__global__ void __launch_bounds__(256) k_mask(const float* __restrict__ proto_p,
                                              const float* __restrict__ coef_p,
                                              const float* __restrict__ box_gt) {
    int b = blockIdx.y, k = blockIdx.x;
    if (k >= g_selcnt[b]) return;
    int p = g_sel[b][k];
    int o = g_pmi[b][p];
    __shared__ float sc[KC_];
    __shared__ float sbox[4];
    if (threadIdx.x < KC_) sc[threadIdx.x] = coef_p[((size_t)(b * P_ + p)) * KC_ + threadIdx.x];
    if (threadIdx.x >= 32 && threadIdx.x < 36)
        sbox[threadIdx.x - 32] = box_gt[(size_t)(b * NOBJ_ + o) * 4 + (threadIdx.x - 32)];
    __syncthreads();
    float bx1 = sbox[0], by1 = sbox[1], bx2 = sbox[2], by2 = sbox[3];

    float ax = bx1 * 138.f, bx = bx2 * 138.f;
    float x1 = fminf(ax, bx), x2 = fmaxf(ax, bx);
    x1 = fmaxf(x1 - 1.f, 0.f); x2 = fminf(x2 + 1.f, 138.f);
    float ay = by1 * 138.f, by = by2 * 138.f;
    float y1 = fminf(ay, by), y2 = fmaxf(ay, by);
    y1 = fmaxf(y1 - 1.f, 0.f); y2 = fminf(y2 + 1.f, 138.f);
    int xlo = (int)ceilf(x1), xhi = (int)ceilf(x2);
    int ylo = (int)ceilf(y1), yhi = (int)ceilf(y2);
    if (xlo < 0) xlo = 0; if (xhi > PW_) xhi = PW_;
    if (ylo < 0) ylo = 0; if (yhi > PH_) yhi = PH_;
    int rw = xhi - xlo, rh = yhi - ylo;
    if (rw < 0) rw = 0; if (rh < 0) rh = 0;
    int rectN = rw * rh;

    const float L = 16.118095651f;
    double zsum = 0.0; int onesIn = 0;
    if (rectN > 0) {
        int dq = 256 / rw, drm = 256 % rw;          // stride decomposition
        int y = ylo + (int)threadIdx.x / rw;
        int x = xlo + (int)threadIdx.x % rw;
        for (int i = threadIdx.x; i < rectN; i += 256) {
            const float4* pr = (const float4*)(proto_p + (((size_t)b * PH_ + y) * PW_ + x) * KC_);
            float z = 0.f;
            #pragma unroll
            for (int q = 0; q < 8; q++) {
                float4 v = pr[q];
                z += v.x * sc[4*q] + v.y * sc[4*q+1] + v.z * sc[4*q+2] + v.w * sc[4*q+3];
            }
            int gt = (g_dm[b][y * PW_ + x] >> o) & 1;
            float zc = fminf(fmaxf(z, -L), L);
            float sp = fmaxf(zc, 0.f) + __logf(1.f + __expf(-fabsf(zc)));
            zsum += (double)(sp - (gt ? zc : 0.f));
            onesIn += gt;
            y += dq; x += drm;
            if (x >= xhi) { x -= rw; y++; }
        }
    }
    double zt = bRedD256(zsum);
    int    ot = bRedI256(onesIn);
    if (threadIdx.x == 0) {
        float A  = -logf(1e-7f);
        float BT = -log1pf(-1e-7f);
        int onesTot  = g_ones[b][o];
        int onesOut  = onesTot - ot;
        int zerosOut = (NPIX_ - rectN) - onesOut;
        double bce = zt + (double)onesOut * (double)A + (double)zerosOut * (double)BT;
        float denom = (bx2 - bx1) * (by2 - by1);
        atomicAdd(&g_mlsum[b], bce / (double)denom);
    }
}

// ------------------------- K8: final combine -------------------------
__global__ void k_final(float* out) {
    if (threadIdx.x == 0) {
        double lm = 0.0;
        for (int b = 0; b < B_; b++) {
            double s = 1.0;
            int np = g_numpos[b];
            if (np > MTT_) {
                float npf = (float)np;
                float nposf = fminf(npf, (float)MTT_);
                s = (double)(npf / fmaxf(nposf, 1.f));
            }
            lm += g_mlsum[b] * s;
        }
        double total = 1.5 * g_acc[0] + g_acc[1] + lm * 6.125 / 138.0 / 138.0;
        out[0] = (float)total;
    }
}

// ------------------------- launch -------------------------
extern "C" void kernel_launch(void* const* d_in, const int* in_sizes, int n_in,
                              void* d_out, int out_size) {
    const float* class_p  = (const float*)d_in[0];
    const float* box_p    = (const float*)d_in[1];
    const float* coef_p   = (const float*)d_in[2];
    const float* proto_p  = (const float*)d_in[3];
    const float* priors   = (const float*)d_in[4];
    const float* box_gt   = (const float*)d_in[5];
    const float* mask_gt  = (const float*)d_in[6];
    const int*   class_gt = (const int*)d_in[7];
    float* out = (float*)d_out;

    cudaFuncSetAttribute(mega3, cudaFuncAttributeMaxDynamicSharedMemorySize, P_ * 4);

    k_init<<<1, 256>>>();
    mega1<<<MATCH_BLOCKS + RESY_BLOCKS, 256>>>(priors, box_gt, class_gt, mask_gt);
    k_override<<<1, 32>>>(class_gt);
    mega2<<<CLASS_BLOCKS + RESX_BLOCKS, 256>>>(class_p, box_p, priors, box_gt);
    mega3<<<16, 512, P_ * 4>>>();
    dim3 gk(MTT_, B_);
    k_mask<<<gk, 256>>>(proto_p, coef_p, box_gt);
    k_final<<<1, 32>>>(out);
}

// round 4
// speedup vs baseline: 1.3000x; 1.1732x over previous
#include <cuda_runtime.h>
#include <math.h>

#define B_    8
#define P_    19248
#define C_    81
#define NOBJ_ 8
#define KC_   32
#define PH_   138
#define PW_   138
#define HH_   550
#define WW_   550
#define NPIX_ (PH_*PW_)
#define MTT_  100
#define SEG3  38   // ceil(P_/512)

// ------------------------- device scratch (static) -------------------------
__device__ double             g_acc[2];          // 0: box-loss raw, 1: conf-loss raw
__device__ double             g_mlsum[B_];
__device__ unsigned long long g_boxkey[B_][NOBJ_];
__device__ int                g_conf[B_][P_];
__device__ unsigned char      g_pmi[B_][P_];
__device__ float              g_mark[B_][P_];
__device__ int                g_numpos[B_];
__device__ float              g_tmp[B_][NOBJ_][PH_][WW_];
__device__ unsigned char      g_dm[B_][NPIX_];
__device__ float              g_wts[PH_][9];
__device__ int                g_wi0[PH_];
__device__ int                g_ones[B_][NOBJ_];
__device__ int                g_sel[B_][MTT_];
__device__ int                g_selcnt[B_];

// ------------------------- reduce / scan helpers (FLOAT hot paths) -------------------------
__device__ __forceinline__ float bRedF256(float v) {
    __shared__ float sd[8];
    int ln = threadIdx.x & 31, wd = threadIdx.x >> 5;
    #pragma unroll
    for (int o = 16; o; o >>= 1) v += __shfl_down_sync(0xffffffffu, v, o);
    if (ln == 0) sd[wd] = v;
    __syncthreads();
    v = (threadIdx.x < 8) ? sd[threadIdx.x] : 0.f;
    if (wd == 0) {
        #pragma unroll
        for (int o = 4; o; o >>= 1) v += __shfl_down_sync(0xffffffffu, v, o);
        if (ln == 0) sd[0] = v;
    }
    __syncthreads();
    float r = sd[0];
    __syncthreads();
    return r;
}
__device__ __forceinline__ int bRedI256(int v) {
    __shared__ int si[8];
    int ln = threadIdx.x & 31, wd = threadIdx.x >> 5;
    #pragma unroll
    for (int o = 16; o; o >>= 1) v += __shfl_down_sync(0xffffffffu, v, o);
    if (ln == 0) si[wd] = v;
    __syncthreads();
    v = (threadIdx.x < 8) ? si[threadIdx.x] : 0;
    if (wd == 0) {
        #pragma unroll
        for (int o = 4; o; o >>= 1) v += __shfl_down_sync(0xffffffffu, v, o);
        if (ln == 0) si[0] = v;
    }
    __syncthreads();
    int r = si[0];
    __syncthreads();
    return r;
}
__device__ __forceinline__ float bRedF512(float v) {
    __shared__ float sd[16];
    int ln = threadIdx.x & 31, wd = threadIdx.x >> 5;
    #pragma unroll
    for (int o = 16; o; o >>= 1) v += __shfl_down_sync(0xffffffffu, v, o);
    if (ln == 0) sd[wd] = v;
    __syncthreads();
    v = (threadIdx.x < 16) ? sd[threadIdx.x] : 0.f;
    if (wd == 0) {
        #pragma unroll
        for (int o = 8; o; o >>= 1) v += __shfl_down_sync(0xffffffffu, v, o);
        if (ln == 0) sd[0] = v;
    }
    __syncthreads();
    float r = sd[0];
    __syncthreads();
    return r;
}
__device__ __forceinline__ int bRedI512(int v) {
    __shared__ int si[16];
    int ln = threadIdx.x & 31, wd = threadIdx.x >> 5;
    #pragma unroll
    for (int o = 16; o; o >>= 1) v += __shfl_down_sync(0xffffffffu, v, o);
    if (ln == 0) si[wd] = v;
    __syncthreads();
    v = (threadIdx.x < 16) ? si[threadIdx.x] : 0;
    if (wd == 0) {
        #pragma unroll
        for (int o = 8; o; o >>= 1) v += __shfl_down_sync(0xffffffffu, v, o);
        if (ln == 0) si[0] = v;
    }
    __syncthreads();
    int r = si[0];
    __syncthreads();
    return r;
}
__device__ __forceinline__ int bScanEx512(int v, int* sh) {
    int tid = threadIdx.x;
    sh[tid] = v;
    __syncthreads();
    #pragma unroll
    for (int off = 1; off < 512; off <<= 1) {
        int t = (tid >= off) ? sh[tid - off] : 0;
        __syncthreads();
        sh[tid] += t;
        __syncthreads();
    }
    int incl = sh[tid];
    __syncthreads();
    return incl - v;
}

// ------------------------- K0: init -------------------------
__global__ void k_init() {
    int t = threadIdx.x;
    if (t < PH_) {
        float inv = (float)(1.0 / (138.0 / 550.0));
        float s = ((float)t + 0.5f) * inv - 0.5f;
        int i0 = (int)ceilf(s - inv);
        int i1 = (int)floorf(s + inv);
        if (i0 < 0) i0 = 0;
        if (i1 > HH_ - 1) i1 = HH_ - 1;
        int cnt = i1 - i0 + 1; if (cnt > 9) cnt = 9;
        float w[9]; float wsum = 0.f;
        #pragma unroll
        for (int k = 0; k < 9; k++) {
            float x = __fdiv_rn(fabsf((float)(i0 + k) - s), inv);
            float wv = fmaxf(0.f, 1.f - x);
            if (k >= cnt) wv = 0.f;
            w[k] = wv; wsum += wv;
        }
        #pragma unroll
        for (int k = 0; k < 9; k++) g_wts[t][k] = __fdiv_rn(w[k], wsum);
        g_wi0[t] = i0;
    }
    if (t < B_ * NOBJ_) {
        ((unsigned long long*)g_boxkey)[t] = 0ull;
        ((int*)g_ones)[t] = 0;
    }
    if (t < B_) { g_numpos[t] = 0; g_mlsum[t] = 0.0; g_selcnt[t] = 0; }
    if (t < 2) g_acc[t] = 0.0;
}

// ------------------------- K1: matching -------------------------
__global__ void __launch_bounds__(256) k_match(const float* __restrict__ priors,
                                               const float* __restrict__ box_gt,
                                               const int* __restrict__ class_gt) {
    int b = blockIdx.y;
    int p = blockIdx.x * 256 + threadIdx.x;
    __shared__ float sbg[NOBJ_][4];
    if (threadIdx.x < NOBJ_ * 4) ((float*)sbg)[threadIdx.x] = box_gt[b * NOBJ_ * 4 + threadIdx.x];
    __syncthreads();

    unsigned long long keys[NOBJ_];
    if (p < P_) {
        float cx = priors[p*4+0], cy = priors[p*4+1], w = priors[p*4+2], h = priors[p*4+3];
        float w2 = __fmul_rn(w, 0.5f), h2 = __fmul_rn(h, 0.5f);
        float dx1 = __fsub_rn(cx, w2), dy1 = __fsub_rn(cy, h2);
        float dx2 = __fadd_rn(cx, w2), dy2 = __fadd_rn(cy, h2);
        float areaP = __fmul_rn(__fsub_rn(dx2, dx1), __fsub_rn(dy2, dy1));
        float best = -1.f; int besto = 0;
        #pragma unroll
        for (int o = 0; o < NOBJ_; o++) {
            float gx1 = sbg[o][0], gy1 = sbg[o][1], gx2 = sbg[o][2], gy2 = sbg[o][3];
            float ix = fmaxf(__fsub_rn(fminf(gx2, dx2), fmaxf(gx1, dx1)), 0.f);
            float iy = fmaxf(__fsub_rn(fminf(gy2, dy2), fmaxf(gy1, dy1)), 0.f);
            float inter = __fmul_rn(ix, iy);
            float areaG = __fmul_rn(__fsub_rn(gx2, gx1), __fsub_rn(gy2, gy1));
            float iou = __fdiv_rn(inter, __fsub_rn(__fadd_rn(areaG, areaP), inter));
            if (iou > best) { best = iou; besto = o; }
            keys[o] = (((unsigned long long)__float_as_uint(iou)) << 32)
                    | (unsigned long long)(0xFFFFFFFFu - (unsigned)p);
        }
        int cg = class_gt[b * NOBJ_ + besto];
        int cf = cg + 1;
        if (best < 0.5f) cf = -1;
        if (best < 0.4f) cf = 0;
        g_conf[b][p] = cf;
        g_pmi[b][p]  = (unsigned char)besto;
    } else {
        #pragma unroll
        for (int o = 0; o < NOBJ_; o++) keys[o] = 0ull;
    }
    #pragma unroll
    for (int o = 0; o < NOBJ_; o++) {
        unsigned long long kk = keys[o];
        #pragma unroll
        for (int off = 16; off; off >>= 1) {
            unsigned long long other = __shfl_down_sync(0xffffffffu, kk, off);
            if (other > kk) kk = other;
        }
        if ((threadIdx.x & 31) == 0) atomicMax(&g_boxkey[b][o], kk);
    }
}

// ------------------------- K1b: forced matches -------------------------
__global__ void k_override(const int* __restrict__ class_gt) {
    int b = threadIdx.x;
    if (b < B_) {
        for (int o = 0; o < NOBJ_; o++) {
            unsigned long long k = g_boxkey[b][o];
            unsigned p = 0xFFFFFFFFu - (unsigned)(k & 0xFFFFFFFFull);
            g_conf[b][p] = class_gt[b * NOBJ_ + o] + 1;
            g_pmi[b][p]  = (unsigned char)o;
        }
    }
}

// ------------------------- K2: class (1 warp / prior) -------------------------
__global__ void __launch_bounds__(256) k_class(const float* __restrict__ class_p,
                                               const float* __restrict__ box_p,
                                               const float* __restrict__ priors,
                                               const float* __restrict__ box_gt) {
    int gw = blockIdx.x * 8 + (threadIdx.x >> 5);
    int lane = threadIdx.x & 31;
    int b = gw / P_, p = gw % P_;
    const float* xp = class_p + (size_t)gw * C_;
    float v0 = xp[lane];
    float v1 = xp[lane + 32];
    float v2 = (lane < C_ - 64) ? xp[lane + 64] : 0.f;
    float m = fmaxf(v0, v1);
    if (lane < C_ - 64) m = fmaxf(m, v2);
    #pragma unroll
    for (int off = 16; off; off >>= 1) m = fmaxf(m, __shfl_xor_sync(0xffffffffu, m, off));
    float s = __expf(v0 - m) + __expf(v1 - m);
    if (lane < C_ - 64) s += __expf(v2 - m);
    #pragma unroll
    for (int off = 16; off; off >>= 1) s += __shfl_xor_sync(0xffffffffu, s, off);
    float lse = m + __logf(s);

    int cf = g_conf[b][p];
    int tgt = cf > 0 ? cf : 0;
    float cand = (tgt < 32) ? v0 : ((tgt < 64) ? v1 : v2);
    float xt = __shfl_sync(0xffffffffu, cand, tgt & 31);
    float x0 = __shfl_sync(0xffffffffu, v0, 0);

    if (lane == 0) {
        bool pos = cf > 0;
        g_mark[b][p] = (pos || cf < 0) ? 0.f : (lse - x0);
        if (pos) {
            atomicAdd(&g_numpos[b], 1);
            int o = g_pmi[b][p];
            const float* bg = box_gt + (size_t)(b * NOBJ_ + o) * 4;
            float mnx = bg[0], mny = bg[1], mxx = bg[2], mxy = bg[3];
            const float* pr = priors + (size_t)p * 4;
            float pcx = pr[0], pcy = pr[1], pw = pr[2], phh = pr[3];
            float off0 = __fdiv_rn(__fsub_rn(__fmul_rn(__fadd_rn(mnx, mxx), 0.5f), pcx), __fmul_rn(0.1f, pw));
            float off1 = __fdiv_rn(__fsub_rn(__fmul_rn(__fadd_rn(mny, mxy), 0.5f), pcy), __fmul_rn(0.1f, phh));
            float off2 = __fdiv_rn(logf(__fdiv_rn(__fsub_rn(mxx, mnx), pw)), 0.2f);
            float off3 = __fdiv_rn(logf(__fdiv_rn(__fsub_rn(mxy, mny), phh)), 0.2f);
            const float* bp = box_p + (size_t)gw * 4;
            float lb = 0.f, d;
            d = fabsf(bp[0] - off0); lb += (d < 1.f) ? 0.5f*d*d : d - 0.5f;
            d = fabsf(bp[1] - off1); lb += (d < 1.f) ? 0.5f*d*d : d - 0.5f;
            d = fabsf(bp[2] - off2); lb += (d < 1.f) ? 0.5f*d*d : d - 0.5f;
            d = fabsf(bp[3] - off3); lb += (d < 1.f) ? 0.5f*d*d : d - 0.5f;
            atomicAdd(&g_acc[0], (double)lb);
            atomicAdd(&g_acc[1], (double)(lse - xt));
        }
    }
}

// ------------------------- K3: select (8 blocks) + pick (8 blocks) -------------------------
__global__ void __launch_bounds__(512) k_selpick() {
    extern __shared__ float smk[];          // P_ floats (select role)
    __shared__ int hist[256];
    __shared__ int sscan[512];
    __shared__ unsigned sh_prefix;
    __shared__ int sh_rem;
    int tid = threadIdx.x;

    if (blockIdx.x < 8) {
        int b = blockIdx.x;
        int np = g_numpos[b];
        long long kll = 3LL * np; if (kll > P_ - 1) kll = P_ - 1;
        if (kll <= 0) return;
        for (int p = tid; p < P_; p += 512) smk[p] = g_mark[b][p];
        if (tid == 0) { sh_prefix = 0u; sh_rem = (int)kll; }
        __syncthreads();

        for (int pass = 0; pass < 4; pass++) {
            int shift = 24 - 8 * pass;
            unsigned himask = (pass == 0) ? 0u : (0xFFFFFFFFu << (shift + 8));
            if (tid < 256) hist[tid] = 0;
            __syncthreads();
            unsigned pref = sh_prefix;
            for (int p = tid; p < P_; p += 512) {
                unsigned u = __float_as_uint(smk[p]);
                if ((u & himask) == pref)
                    atomicAdd(&hist[(u >> shift) & 255], 1);
            }
            __syncthreads();
            if (tid == 0) {
                int rem = sh_rem;
                int cum = 0, bin = 255;
                for (; bin > 0; bin--) {
                    cum += hist[bin];
                    if (cum >= rem) break;
                }
                if (cum < rem) cum += hist[0];
                sh_rem = rem - (cum - hist[bin]);
                sh_prefix = pref | ((unsigned)bin << shift);
            }
            __syncthreads();
        }
        unsigned tb = sh_prefix;
        int quota = sh_rem;

        float sgt = 0.f, seq = 0.f; int ceq = 0;
        for (int p = tid; p < P_; p += 512) {
            float v = smk[p];
            unsigned u = __float_as_uint(v);
            if (u > tb) sgt += v;
            else if (u == tb) { seq += v; ceq++; }
        }
        float sgt_t = bRedF512(sgt);
        float seq_t = bRedF512(seq);
        int   ceq_t = bRedI512(ceq);
        bool ordered = (ceq_t != quota) && (tb != 0u);
        if (tid == 0) atomicAdd(&g_acc[1], (double)(sgt_t + (ordered ? 0.f : seq_t)));

        if (ordered) {
            int s0 = tid * SEG3, s1 = s0 + SEG3; if (s1 > P_) s1 = P_;
            int c = 0;
            for (int p = s0; p < s1; p++)
                if (__float_as_uint(smk[p]) == tb) c++;
            int pre = bScanEx512(c, sscan);
            float sord = 0.f; int r = pre;
            for (int p = s0; p < s1; p++) {
                if (__float_as_uint(smk[p]) == tb) {
                    if (r < quota) sord += smk[p];
                    r++;
                }
            }
            float st = bRedF512(sord);
            if (tid == 0) atomicAdd(&g_acc[1], (double)st);
        }
    } else {
        int b = blockIdx.x - 8;
        int np = g_numpos[b];
        int cap = np < MTT_ ? np : MTT_;
        if (tid == 0) g_selcnt[b] = cap;
        int s0 = tid * SEG3, s1 = s0 + SEG3; if (s1 > P_) s1 = P_;
        int c = 0;
        for (int p = s0; p < s1; p++)
            if (g_conf[b][p] > 0) c++;
        int pre = bScanEx512(c, sscan);
        int r = pre;
        for (int p = s0; p < s1; p++) {
            if (g_conf[b][p] > 0) {
                if (r < cap) g_sel[b][r] = p;
                r++;
            }
        }
    }
}

// ------------------------- K4a: resize y -------------------------
__global__ void __launch_bounds__(256) k_resize_y(const float* __restrict__ mg) {
    int id = blockIdx.x;
    int yo = id % PH_; id /= PH_;
    int o  = id % NOBJ_;
    int b  = id / NOBJ_;
    int i0 = g_wi0[yo];
    float w[9];
    #pragma unroll
    for (int t = 0; t < 9; t++) w[t] = g_wts[yo][t];
    const float* src = mg + ((size_t)(b * NOBJ_ + o)) * HH_ * WW_;
    const float* rows[9];
    #pragma unroll
    for (int t = 0; t < 9; t++) {
        int yi = i0 + t; if (yi > HH_ - 1) yi = HH_ - 1;
        rows[t] = src + (size_t)yi * WW_;
    }
    float* dst = &g_tmp[b][o][yo][0];
    for (int x = threadIdx.x; x < WW_; x += 256) {
        float s = 0.f;
        #pragma unroll
        for (int t = 0; t < 9; t++) s += w[t] * rows[t][x];
        dst[x] = s;
    }
}

// ------------------------- K4b: resize x (block per (b,yo), smem-staged) -------------------------
__global__ void __launch_bounds__(256) k_resize_x() {
    __shared__ float srow[NOBJ_][WW_];
    __shared__ int shc[NOBJ_];
    int b  = blockIdx.x / PH_;
    int yo = blockIdx.x % PH_;
    int tid = threadIdx.x;
    #pragma unroll
    for (int o = 0; o < NOBJ_; o++)
        for (int x = tid; x < WW_; x += 256)
            srow[o][x] = g_tmp[b][o][yo][x];
    if (tid < NOBJ_) shc[tid] = 0;
    __syncthreads();

    unsigned bits = 0;
    if (tid < PW_) {
        int i0 = g_wi0[tid];
        float w[9];
        #pragma unroll
        for (int t = 0; t < 9; t++) w[t] = g_wts[tid][t];
        #pragma unroll
        for (int o = 0; o < NOBJ_; o++) {
            float s = 0.f;
            #pragma unroll
            for (int t = 0; t < 9; t++) {
                int xi = i0 + t; if (xi > WW_ - 1) xi = WW_ - 1;
                s += w[t] * srow[o][xi];
            }
            if (s > 0.5f) bits |= (1u << o);
        }
        g_dm[b][yo * PW_ + tid] = (unsigned char)bits;
    }
    int lane = tid & 31;
    #pragma unroll
    for (int o = 0; o < NOBJ_; o++) {
        unsigned mb = __ballot_sync(0xffffffffu, (bits >> o) & 1);
        if (lane == 0 && mb) atomicAdd(&shc[o], __popc(mb));
    }
    __syncthreads();
    if (tid < NOBJ_ && shc[tid]) atomicAdd(&g_ones[b][tid], shc[tid]);
}

// ------------------------- K5: mask BCE (float accumulation) -------------------------
__global__ void __launch_bounds__(256) k_mask(const float* __restrict__ proto_p,
                                              const float* __restrict__ coef_p,
                                              const float* __restrict__ box_gt) {
    int b = blockIdx.y, k = blockIdx.x;
    if (k >= g_selcnt[b]) return;
    int p = g_sel[b][k];
    int o = g_pmi[b][p];
    __shared__ float sc[KC_];
    __shared__ float sbox[4];
    if (threadIdx.x < KC_) sc[threadIdx.x] = coef_p[((size_t)(b * P_ + p)) * KC_ + threadIdx.x];
    if (threadIdx.x >= 32 && threadIdx.x < 36)
        sbox[threadIdx.x - 32] = box_gt[(size_t)(b * NOBJ_ + o) * 4 + (threadIdx.x - 32)];
    __syncthreads();
    float bx1 = sbox[0], by1 = sbox[1], bx2 = sbox[2], by2 = sbox[3];

    float ax = bx1 * 138.f, bx = bx2 * 138.f;
    float x1 = fminf(ax, bx), x2 = fmaxf(ax, bx);
    x1 = fmaxf(x1 - 1.f, 0.f); x2 = fminf(x2 + 1.f, 138.f);
    float ay = by1 * 138.f, by = by2 * 138.f;
    float y1 = fminf(ay, by), y2 = fmaxf(ay, by);
    y1 = fmaxf(y1 - 1.f, 0.f); y2 = fminf(y2 + 1.f, 138.f);
    int xlo = (int)ceilf(x1), xhi = (int)ceilf(x2);
    int ylo = (int)ceilf(y1), yhi = (int)ceilf(y2);
    if (xlo < 0) xlo = 0; if (xhi > PW_) xhi = PW_;
    if (ylo < 0) ylo = 0; if (yhi > PH_) yhi = PH_;
    int rw = xhi - xlo, rh = yhi - ylo;
    if (rw < 0) rw = 0; if (rh < 0) rh = 0;
    int rectN = rw * rh;

    const float L = 16.118095651f;
    float zsum = 0.f; int onesIn = 0;
    if (rectN > 0) {
        int dq = 256 / rw, drm = 256 % rw;
        int y = ylo + (int)threadIdx.x / rw;
        int x = xlo + (int)threadIdx.x % rw;
        for (int i = threadIdx.x; i < rectN; i += 256) {
            const float4* pr = (const float4*)(proto_p + (((size_t)b * PH_ + y) * PW_ + x) * KC_);
            float z = 0.f;
            #pragma unroll
            for (int q = 0; q < 8; q++) {
                float4 v = pr[q];
                z += v.x * sc[4*q] + v.y * sc[4*q+1] + v.z * sc[4*q+2] + v.w * sc[4*q+3];
            }
            int gt = (g_dm[b][y * PW_ + x] >> o) & 1;
            float zc = fminf(fmaxf(z, -L), L);
            float sp = fmaxf(zc, 0.f) + __logf(1.f + __expf(-fabsf(zc)));
            zsum += sp - (gt ? zc : 0.f);
            onesIn += gt;
            y += dq; x += drm;
            if (x >= xhi) { x -= rw; y++; }
        }
    }
    float zt = bRedF256(zsum);
    int   ot = bRedI256(onesIn);
    if (threadIdx.x == 0) {
        float A  = -logf(1e-7f);
        float BT = -log1pf(-1e-7f);
        int onesTot  = g_ones[b][o];
        int onesOut  = onesTot - ot;
        int zerosOut = (NPIX_ - rectN) - onesOut;
        double bce = (double)zt + (double)onesOut * (double)A + (double)zerosOut * (double)BT;
        float denom = (bx2 - bx1) * (by2 - by1);
        atomicAdd(&g_mlsum[b], bce / (double)denom);
    }
}

// ------------------------- K6: final combine -------------------------
__global__ void k_final(float* out) {
    if (threadIdx.x == 0) {
        double lm = 0.0;
        for (int b = 0; b < B_; b++) {
            double s = 1.0;
            int np = g_numpos[b];
            if (np > MTT_) {
                float npf = (float)np;
                float nposf = fminf(npf, (float)MTT_);
                s = (double)(npf / fmaxf(nposf, 1.f));
            }
            lm += g_mlsum[b] * s;
        }
        double total = 1.5 * g_acc[0] + g_acc[1] + lm * 6.125 / 138.0 / 138.0;
        out[0] = (float)total;
    }
}

// ------------------------- launch (two-stream fork/join) -------------------------
extern "C" void kernel_launch(void* const* d_in, const int* in_sizes, int n_in,
                              void* d_out, int out_size) {
    const float* class_p  = (const float*)d_in[0];
    const float* box_p    = (const float*)d_in[1];
    const float* coef_p   = (const float*)d_in[2];
    const float* proto_p  = (const float*)d_in[3];
    const float* priors   = (const float*)d_in[4];
    const float* box_gt   = (const float*)d_in[5];
    const float* mask_gt  = (const float*)d_in[6];
    const int*   class_gt = (const int*)d_in[7];
    float* out = (float*)d_out;

    static cudaStream_t s2 = nullptr;
    static cudaEvent_t  e0 = nullptr, e1 = nullptr;
    if (!s2) {
        cudaStreamCreateWithFlags(&s2, cudaStreamNonBlocking);
        cudaEventCreateWithFlags(&e0, cudaEventDisableTiming);
        cudaEventCreateWithFlags(&e1, cudaEventDisableTiming);
        cudaFuncSetAttribute(k_selpick, cudaFuncAttributeMaxDynamicSharedMemorySize, P_ * 4);
    }

    k_init<<<1, 256>>>();
    cudaEventRecord(e0, 0);
    cudaStreamWaitEvent(s2, e0, 0);

    // stream B: mask-GT resize chain
    k_resize_y<<<B_ * NOBJ_ * PH_, 256, 0, s2>>>(mask_gt);
    k_resize_x<<<B_ * PH_, 256, 0, s2>>>();
    cudaEventRecord(e1, s2);

    // main stream: match -> class -> select/pick
    dim3 gm((P_ + 255) / 256, B_);
    k_match<<<gm, 256>>>(priors, box_gt, class_gt);
    k_override<<<1, 32>>>(class_gt);
    k_class<<<(B_ * P_) / 8, 256>>>(class_p, box_p, priors, box_gt);
    k_selpick<<<16, 512, P_ * 4>>>();

    cudaStreamWaitEvent(0, e1, 0);
    dim3 gk(MTT_, B_);
    k_mask<<<gk, 256>>>(proto_p, coef_p, box_gt);
    k_final<<<1, 32>>>(out);
}

// round 5
// speedup vs baseline: 1.5137x; 1.1644x over previous
#include <cuda_runtime.h>
#include <math.h>

#define B_    8
#define P_    19248
#define C_    81
#define NOBJ_ 8
#define KC_   32
#define PH_   138
#define PW_   138
#define HH_   550
#define WW_   550
#define NPIX_ (PH_*PW_)
#define MTT_  100
#define SEG3  38   // ceil(P_/512)
#define MBLK  76   // ceil(P_/256)

// ------------------------- device scratch (static) -------------------------
__device__ double             g_acc[2];          // 0: box raw, 1: conf raw
__device__ double             g_mlsum[B_];
__device__ unsigned long long g_boxkey[B_][NOBJ_];
__device__ int                g_conf[B_][P_];
__device__ unsigned char      g_pmi[B_][P_];
__device__ float              g_mark[B_][P_];
__device__ float              g_lse[B_][P_];
__device__ int                g_numpos[B_];
__device__ unsigned char      g_dm[B_][NPIX_];
__device__ float              g_wts[PH_][9];
__device__ int                g_wi0[PH_];
__device__ int                g_ones[B_][NOBJ_];
__device__ int                g_sel[B_][MTT_];
__device__ int                g_selcnt[B_];

// ------------------------- reduce / scan helpers -------------------------
__device__ __forceinline__ float bRedF256(float v) {
    __shared__ float sd[8];
    int ln = threadIdx.x & 31, wd = threadIdx.x >> 5;
    #pragma unroll
    for (int o = 16; o; o >>= 1) v += __shfl_down_sync(0xffffffffu, v, o);
    if (ln == 0) sd[wd] = v;
    __syncthreads();
    v = (threadIdx.x < 8) ? sd[threadIdx.x] : 0.f;
    if (wd == 0) {
        #pragma unroll
        for (int o = 4; o; o >>= 1) v += __shfl_down_sync(0xffffffffu, v, o);
        if (ln == 0) sd[0] = v;
    }
    __syncthreads();
    float r = sd[0];
    __syncthreads();
    return r;
}
__device__ __forceinline__ int bRedI256(int v) {
    __shared__ int si[8];
    int ln = threadIdx.x & 31, wd = threadIdx.x >> 5;
    #pragma unroll
    for (int o = 16; o; o >>= 1) v += __shfl_down_sync(0xffffffffu, v, o);
    if (ln == 0) si[wd] = v;
    __syncthreads();
    v = (threadIdx.x < 8) ? si[threadIdx.x] : 0;
    if (wd == 0) {
        #pragma unroll
        for (int o = 4; o; o >>= 1) v += __shfl_down_sync(0xffffffffu, v, o);
        if (ln == 0) si[0] = v;
    }
    __syncthreads();
    int r = si[0];
    __syncthreads();
    return r;
}
__device__ __forceinline__ float bRedF512(float v) {
    __shared__ float sd[16];
    int ln = threadIdx.x & 31, wd = threadIdx.x >> 5;
    #pragma unroll
    for (int o = 16; o; o >>= 1) v += __shfl_down_sync(0xffffffffu, v, o);
    if (ln == 0) sd[wd] = v;
    __syncthreads();
    v = (threadIdx.x < 16) ? sd[threadIdx.x] : 0.f;
    if (wd == 0) {
        #pragma unroll
        for (int o = 8; o; o >>= 1) v += __shfl_down_sync(0xffffffffu, v, o);
        if (ln == 0) sd[0] = v;
    }
    __syncthreads();
    float r = sd[0];
    __syncthreads();
    return r;
}
__device__ __forceinline__ int bRedI512(int v) {
    __shared__ int si[16];
    int ln = threadIdx.x & 31, wd = threadIdx.x >> 5;
    #pragma unroll
    for (int o = 16; o; o >>= 1) v += __shfl_down_sync(0xffffffffu, v, o);
    if (ln == 0) si[wd] = v;
    __syncthreads();
    v = (threadIdx.x < 16) ? si[threadIdx.x] : 0;
    if (wd == 0) {
        #pragma unroll
        for (int o = 8; o; o >>= 1) v += __shfl_down_sync(0xffffffffu, v, o);
        if (ln == 0) si[0] = v;
    }
    __syncthreads();
    int r = si[0];
    __syncthreads();
    return r;
}
__device__ __forceinline__ int bScanEx512(int v, int* sh) {
    int tid = threadIdx.x;
    sh[tid] = v;
    __syncthreads();
    #pragma unroll
    for (int off = 1; off < 512; off <<= 1) {
        int t = (tid >= off) ? sh[tid - off] : 0;
        __syncthreads();
        sh[tid] += t;
        __syncthreads();
    }
    int incl = sh[tid];
    __syncthreads();
    return incl - v;
}

// ------------------------- K0: init -------------------------
__global__ void k_init() {
    int t = threadIdx.x;
    if (t < PH_) {
        float inv = (float)(1.0 / (138.0 / 550.0));
        float s = ((float)t + 0.5f) * inv - 0.5f;
        int i0 = (int)ceilf(s - inv);
        int i1 = (int)floorf(s + inv);
        if (i0 < 0) i0 = 0;
        if (i1 > HH_ - 1) i1 = HH_ - 1;
        int cnt = i1 - i0 + 1; if (cnt > 9) cnt = 9;
        float w[9]; float wsum = 0.f;
        #pragma unroll
        for (int k = 0; k < 9; k++) {
            float x = __fdiv_rn(fabsf((float)(i0 + k) - s), inv);
            float wv = fmaxf(0.f, 1.f - x);
            if (k >= cnt) wv = 0.f;
            w[k] = wv; wsum += wv;
        }
        #pragma unroll
        for (int k = 0; k < 9; k++) g_wts[t][k] = __fdiv_rn(w[k], wsum);
        g_wi0[t] = i0;
    }
    if (t < B_ * NOBJ_) {
        ((unsigned long long*)g_boxkey)[t] = 0ull;
        ((int*)g_ones)[t] = 0;
    }
    if (t < B_) { g_numpos[t] = 0; g_mlsum[t] = 0.0; g_selcnt[t] = 0; }
    if (t < 2) g_acc[t] = 0.0;
}

// ------------------------- K1: matching (redux + smem staging) -------------------------
__global__ void __launch_bounds__(256) k_match(const float* __restrict__ priors,
                                               const float* __restrict__ box_gt,
                                               const int* __restrict__ class_gt) {
    int b = blockIdx.y;
    int tid = threadIdx.x;
    int p = blockIdx.x * 256 + tid;
    bool valid = p < P_;
    int lane = tid & 31;
    __shared__ float sbg[NOBJ_][4];
    __shared__ unsigned long long skey[NOBJ_];
    if (tid < NOBJ_ * 4) ((float*)sbg)[tid] = box_gt[b * NOBJ_ * 4 + tid];
    if (tid < NOBJ_) skey[tid] = 0ull;
    __syncthreads();

    float dx1 = 0.f, dy1 = 0.f, dx2 = 0.f, dy2 = 0.f, areaP = 0.f;
    if (valid) {
        float4 pr = ((const float4*)priors)[p];
        float w2 = __fmul_rn(pr.z, 0.5f), h2 = __fmul_rn(pr.w, 0.5f);
        dx1 = __fsub_rn(pr.x, w2); dy1 = __fsub_rn(pr.y, h2);
        dx2 = __fadd_rn(pr.x, w2); dy2 = __fadd_rn(pr.y, h2);
        areaP = __fmul_rn(__fsub_rn(dx2, dx1), __fsub_rn(dy2, dy1));
    }
    float best = -1.f; int besto = 0;
    #pragma unroll
    for (int o = 0; o < NOBJ_; o++) {
        unsigned u = 0u;
        if (valid) {
            float gx1 = sbg[o][0], gy1 = sbg[o][1], gx2 = sbg[o][2], gy2 = sbg[o][3];
            float ix = fmaxf(__fsub_rn(fminf(gx2, dx2), fmaxf(gx1, dx1)), 0.f);
            float iy = fmaxf(__fsub_rn(fminf(gy2, dy2), fmaxf(gy1, dy1)), 0.f);
            float inter = __fmul_rn(ix, iy);
            float areaG = __fmul_rn(__fsub_rn(gx2, gx1), __fsub_rn(gy2, gy1));
            float iou = __fdiv_rn(inter, __fsub_rn(__fadd_rn(areaG, areaP), inter));
            if (iou > best) { best = iou; besto = o; }
            u = __float_as_uint(iou);
        }
        unsigned wmax = __reduce_max_sync(0xffffffffu, u);
        unsigned bal = __ballot_sync(0xffffffffu, u == wmax);
        int leader = __ffs(bal) - 1;
        if (lane == leader && valid)
            atomicMax(&skey[o], (((unsigned long long)u) << 32)
                               | (unsigned long long)(0xFFFFFFFFu - (unsigned)p));
    }
    if (valid) {
        int cg = class_gt[b * NOBJ_ + besto];
        int cf = cg + 1;
        if (best < 0.5f) cf = -1;
        if (best < 0.4f) cf = 0;
        g_conf[b][p] = cf;
        g_pmi[b][p]  = (unsigned char)besto;
    }
    __syncthreads();
    if (tid < NOBJ_ && skey[tid]) atomicMax(&g_boxkey[b][tid], skey[tid]);
}

// ------------------------- K1b: forced matches -------------------------
__global__ void k_override(const int* __restrict__ class_gt) {
    int b = threadIdx.x;
    if (b < B_) {
        for (int o = 0; o < NOBJ_; o++) {
            unsigned long long k = g_boxkey[b][o];
            unsigned p = 0xFFFFFFFFu - (unsigned)(k & 0xFFFFFFFFull);
            g_conf[b][p] = class_gt[b * NOBJ_ + o] + 1;
            g_pmi[b][p]  = (unsigned char)o;
        }
    }
}

// ------------------------- K2: lse/mark sweep (independent of matching) -------------------------
__global__ void __launch_bounds__(256) k_lse(const float* __restrict__ class_p) {
    int gw = blockIdx.x * 8 + (threadIdx.x >> 5);
    int lane = threadIdx.x & 31;
    const float* xp = class_p + (size_t)gw * C_;
    float v0 = xp[lane];
    float v1 = xp[lane + 32];
    float v2 = (lane < C_ - 64) ? xp[lane + 64] : 0.f;
    float s = __expf(v0) + __expf(v1);
    if (lane < C_ - 64) s += __expf(v2);
    #pragma unroll
    for (int off = 16; off; off >>= 1) s += __shfl_xor_sync(0xffffffffu, s, off);
    float lse = __logf(s);
    float x0 = __shfl_sync(0xffffffffu, v0, 0);
    if (lane == 0) {
        int b = gw / P_, p = gw % P_;
        g_lse[b][p]  = lse;
        g_mark[b][p] = lse - x0;
    }
}

// ------------------------- K3: positive losses + numpos -------------------------
__global__ void __launch_bounds__(256) k_posloss(const float* __restrict__ class_p,
                                                 const float* __restrict__ box_p,
                                                 const float* __restrict__ priors,
                                                 const float* __restrict__ box_gt) {
    int b = blockIdx.y;
    int p = blockIdx.x * 256 + threadIdx.x;
    int lane = threadIdx.x & 31;
    bool pos = false;
    int cf = 0;
    if (p < P_) { cf = g_conf[b][p]; pos = cf > 0; }

    float lb = 0.f, nll = 0.f;
    if (pos) {
        float lse = g_lse[b][p];
        float xt = class_p[((size_t)(b * P_ + p)) * C_ + cf];
        nll = lse - xt;
        int o = g_pmi[b][p];
        const float* bg = box_gt + (size_t)(b * NOBJ_ + o) * 4;
        float mnx = bg[0], mny = bg[1], mxx = bg[2], mxy = bg[3];
        float4 pr = ((const float4*)priors)[p];
        float off0 = __fdiv_rn(__fsub_rn(__fmul_rn(__fadd_rn(mnx, mxx), 0.5f), pr.x), __fmul_rn(0.1f, pr.z));
        float off1 = __fdiv_rn(__fsub_rn(__fmul_rn(__fadd_rn(mny, mxy), 0.5f), pr.y), __fmul_rn(0.1f, pr.w));
        float off2 = __fdiv_rn(logf(__fdiv_rn(__fsub_rn(mxx, mnx), pr.z)), 0.2f);
        float off3 = __fdiv_rn(logf(__fdiv_rn(__fsub_rn(mxy, mny), pr.w)), 0.2f);
        const float4 bp = ((const float4*)box_p)[b * P_ + p];
        float d;
        d = fabsf(bp.x - off0); lb += (d < 1.f) ? 0.5f*d*d : d - 0.5f;
        d = fabsf(bp.y - off1); lb += (d < 1.f) ? 0.5f*d*d : d - 0.5f;
        d = fabsf(bp.z - off2); lb += (d < 1.f) ? 0.5f*d*d : d - 0.5f;
        d = fabsf(bp.w - off3); lb += (d < 1.f) ? 0.5f*d*d : d - 0.5f;
    }
    unsigned bal = __ballot_sync(0xffffffffu, pos);
    #pragma unroll
    for (int off = 16; off; off >>= 1) {
        lb  += __shfl_down_sync(0xffffffffu, lb, off);
        nll += __shfl_down_sync(0xffffffffu, nll, off);
    }
    if (lane == 0 && bal) {
        atomicAdd(&g_numpos[b], __popc(bal));
        atomicAdd(&g_acc[0], (double)lb);
        atomicAdd(&g_acc[1], (double)nll);
    }
}

// ------------------------- K4: select (8 blocks) + pick (8 blocks) -------------------------
__global__ void __launch_bounds__(512) k_selpick() {
    extern __shared__ float smk[];
    __shared__ int hist[256];
    __shared__ int sscan[512];
    __shared__ unsigned sh_prefix;
    __shared__ int sh_rem;
    int tid = threadIdx.x;

    if (blockIdx.x < 8) {
        int b = blockIdx.x;
        int np = g_numpos[b];
        long long kll = 3LL * np; if (kll > P_ - 1) kll = P_ - 1;
        if (kll <= 0) return;
        for (int p = tid; p < P_; p += 512) {
            float v = (g_conf[b][p] == 0) ? g_mark[b][p] : 0.f;
            smk[p] = v;
        }
        if (tid == 0) { sh_prefix = 0u; sh_rem = (int)kll; }
        __syncthreads();

        for (int pass = 0; pass < 4; pass++) {
            int shift = 24 - 8 * pass;
            unsigned himask = (pass == 0) ? 0u : (0xFFFFFFFFu << (shift + 8));
            if (tid < 256) hist[tid] = 0;
            __syncthreads();
            unsigned pref = sh_prefix;
            for (int p = tid; p < P_; p += 512) {
                unsigned u = __float_as_uint(smk[p]);
                if ((u & himask) == pref)
                    atomicAdd(&hist[(u >> shift) & 255], 1);
            }
            __syncthreads();
            if (tid == 0) {
                int rem = sh_rem;
                int cum = 0, bin = 255;
                for (; bin > 0; bin--) {
                    cum += hist[bin];
                    if (cum >= rem) break;
                }
                if (cum < rem) cum += hist[0];
                sh_rem = rem - (cum - hist[bin]);
                sh_prefix = pref | ((unsigned)bin << shift);
            }
            __syncthreads();
        }
        unsigned tb = sh_prefix;
        int quota = sh_rem;

        float sgt = 0.f, seq = 0.f; int ceq = 0;
        for (int p = tid; p < P_; p += 512) {
            float v = smk[p];
            unsigned u = __float_as_uint(v);
            if (u > tb) sgt += v;
            else if (u == tb) { seq += v; ceq++; }
        }
        float sgt_t = bRedF512(sgt);
        float seq_t = bRedF512(seq);
        int   ceq_t = bRedI512(ceq);
        bool ordered = (ceq_t != quota) && (tb != 0u);
        if (tid == 0) atomicAdd(&g_acc[1], (double)(sgt_t + (ordered ? 0.f : seq_t)));

        if (ordered) {
            int s0 = tid * SEG3, s1 = s0 + SEG3; if (s1 > P_) s1 = P_;
            int c = 0;
            for (int p = s0; p < s1; p++)
                if (__float_as_uint(smk[p]) == tb) c++;
            int pre = bScanEx512(c, sscan);
            float sord = 0.f; int r = pre;
            for (int p = s0; p < s1; p++) {
                if (__float_as_uint(smk[p]) == tb) {
                    if (r < quota) sord += smk[p];
                    r++;
                }
            }
            float st = bRedF512(sord);
            if (tid == 0) atomicAdd(&g_acc[1], (double)st);
        }
    } else {
        int b = blockIdx.x - 8;
        int np = g_numpos[b];
        int cap = np < MTT_ ? np : MTT_;
        if (tid == 0) g_selcnt[b] = cap;
        int s0 = tid * SEG3, s1 = s0 + SEG3; if (s1 > P_) s1 = P_;
        int c = 0;
        for (int p = s0; p < s1; p++)
            if (g_conf[b][p] > 0) c++;
        int pre = bScanEx512(c, sscan);
        int r = pre;
        for (int p = s0; p < s1; p++) {
            if (g_conf[b][p] > 0) {
                if (r < cap) g_sel[b][r] = p;
                r++;
            }
        }
    }
}

// ------------------------- K5: fused resize (y+x), block per (b, yo) -------------------------
__global__ void __launch_bounds__(256) k_resize(const float* __restrict__ mg) {
    __shared__ float srow[NOBJ_][WW_];
    __shared__ int shc[NOBJ_];
    int b  = blockIdx.x / PH_;
    int yo = blockIdx.x % PH_;
    int tid = threadIdx.x;
    int i0 = g_wi0[yo];
    float wy[9];
    #pragma unroll
    for (int t = 0; t < 9; t++) wy[t] = g_wts[yo][t];
    if (tid < NOBJ_) shc[tid] = 0;

    #pragma unroll
    for (int o = 0; o < NOBJ_; o++) {
        const float* src = mg + ((size_t)(b * NOBJ_ + o)) * HH_ * WW_;
        const float* rows[9];
        #pragma unroll
        for (int t = 0; t < 9; t++) {
            int yi = i0 + t; if (yi > HH_ - 1) yi = HH_ - 1;
            rows[t] = src + (size_t)yi * WW_;
        }
        for (int x = tid; x < WW_; x += 256) {
            float s = 0.f;
            #pragma unroll
            for (int t = 0; t < 9; t++) s += wy[t] * rows[t][x];
            srow[o][x] = s;
        }
    }
    __syncthreads();

    unsigned bits = 0;
    if (tid < PW_) {
        int j0 = g_wi0[tid];
        float wx[9];
        #pragma unroll
        for (int t = 0; t < 9; t++) wx[t] = g_wts[tid][t];
        #pragma unroll
        for (int o = 0; o < NOBJ_; o++) {
            float s = 0.f;
            #pragma unroll
            for (int t = 0; t < 9; t++) {
                int xi = j0 + t; if (xi > WW_ - 1) xi = WW_ - 1;
                s += wx[t] * srow[o][xi];
            }
            if (s > 0.5f) bits |= (1u << o);
        }
        g_dm[b][yo * PW_ + tid] = (unsigned char)bits;
    }
    int lane = tid & 31;
    #pragma unroll
    for (int o = 0; o < NOBJ_; o++) {
        unsigned mb = __ballot_sync(0xffffffffu, (bits >> o) & 1);
        if (lane == 0 && mb) atomicAdd(&shc[o], __popc(mb));
    }
    __syncthreads();
    if (tid < NOBJ_ && shc[tid]) atomicAdd(&g_ones[b][tid], shc[tid]);
}

// ------------------------- K6: mask BCE -------------------------
__global__ void __launch_bounds__(256) k_mask(const float* __restrict__ proto_p,
                                              const float* __restrict__ coef_p,
                                              const float* __restrict__ box_gt) {
    int b = blockIdx.y, k = blockIdx.x;
    if (k >= g_selcnt[b]) return;
    int p = g_sel[b][k];
    int o = g_pmi[b][p];
    __shared__ float sc[KC_];
    __shared__ float sbox[4];
    if (threadIdx.x < KC_) sc[threadIdx.x] = coef_p[((size_t)(b * P_ + p)) * KC_ + threadIdx.x];
    if (threadIdx.x >= 32 && threadIdx.x < 36)
        sbox[threadIdx.x - 32] = box_gt[(size_t)(b * NOBJ_ + o) * 4 + (threadIdx.x - 32)];
    __syncthreads();
    float bx1 = sbox[0], by1 = sbox[1], bx2 = sbox[2], by2 = sbox[3];

    float ax = bx1 * 138.f, bx = bx2 * 138.f;
    float x1 = fminf(ax, bx), x2 = fmaxf(ax, bx);
    x1 = fmaxf(x1 - 1.f, 0.f); x2 = fminf(x2 + 1.f, 138.f);
    float ay = by1 * 138.f, by = by2 * 138.f;
    float y1 = fminf(ay, by), y2 = fmaxf(ay, by);
    y1 = fmaxf(y1 - 1.f, 0.f); y2 = fminf(y2 + 1.f, 138.f);
    int xlo = (int)ceilf(x1), xhi = (int)ceilf(x2);
    int ylo = (int)ceilf(y1), yhi = (int)ceilf(y2);
    if (xlo < 0) xlo = 0; if (xhi > PW_) xhi = PW_;
    if (ylo < 0) ylo = 0; if (yhi > PH_) yhi = PH_;
    int rw = xhi - xlo, rh = yhi - ylo;
    if (rw < 0) rw = 0; if (rh < 0) rh = 0;
    int rectN = rw * rh;

    const float L = 16.118095651f;
    float zsum = 0.f; int onesIn = 0;
    if (rectN > 0) {
        int dq = 256 / rw, drm = 256 % rw;
        int y = ylo + (int)threadIdx.x / rw;
        int x = xlo + (int)threadIdx.x % rw;
        for (int i = threadIdx.x; i < rectN; i += 256) {
            const float4* pr = (const float4*)(proto_p + (((size_t)b * PH_ + y) * PW_ + x) * KC_);
            float z = 0.f;
            #pragma unroll
            for (int q = 0; q < 8; q++) {
                float4 v = pr[q];
                z += v.x * sc[4*q] + v.y * sc[4*q+1] + v.z * sc[4*q+2] + v.w * sc[4*q+3];
            }
            int gt = (g_dm[b][y * PW_ + x] >> o) & 1;
            float zc = fminf(fmaxf(z, -L), L);
            float sp = fmaxf(zc, 0.f) + __logf(1.f + __expf(-fabsf(zc)));
            zsum += sp - (gt ? zc : 0.f);
            onesIn += gt;
            y += dq; x += drm;
            if (x >= xhi) { x -= rw; y++; }
        }
    }
    float zt = bRedF256(zsum);
    int   ot = bRedI256(onesIn);
    if (threadIdx.x == 0) {
        float A  = -logf(1e-7f);
        float BT = -log1pf(-1e-7f);
        int onesTot  = g_ones[b][o];
        int onesOut  = onesTot - ot;
        int zerosOut = (NPIX_ - rectN) - onesOut;
        double bce = (double)zt + (double)onesOut * (double)A + (double)zerosOut * (double)BT;
        float denom = (bx2 - bx1) * (by2 - by1);
        atomicAdd(&g_mlsum[b], bce / (double)denom);
    }
}

// ------------------------- K7: final combine -------------------------
__global__ void k_final(float* out) {
    if (threadIdx.x == 0) {
        double lm = 0.0;
        for (int b = 0; b < B_; b++) {
            double s = 1.0;
            int np = g_numpos[b];
            if (np > MTT_) {
                float npf = (float)np;
                float nposf = fminf(npf, (float)MTT_);
                s = (double)(npf / fmaxf(nposf, 1.f));
            }
            lm += g_mlsum[b] * s;
        }
        double total = 1.5 * g_acc[0] + g_acc[1] + lm * 6.125 / 138.0 / 138.0;
        out[0] = (float)total;
    }
}

// ------------------------- launch (3-stream fork/join) -------------------------
extern "C" void kernel_launch(void* const* d_in, const int* in_sizes, int n_in,
                              void* d_out, int out_size) {
    const float* class_p  = (const float*)d_in[0];
    const float* box_p    = (const float*)d_in[1];
    const float* coef_p   = (const float*)d_in[2];
    const float* proto_p  = (const float*)d_in[3];
    const float* priors   = (const float*)d_in[4];
    const float* box_gt   = (const float*)d_in[5];
    const float* mask_gt  = (const float*)d_in[6];
    const int*   class_gt = (const int*)d_in[7];
    float* out = (float*)d_out;

    static cudaStream_t s2 = nullptr, s3 = nullptr;
    static cudaEvent_t  e0 = nullptr, e2 = nullptr, e3 = nullptr;
    if (!s2) {
        cudaStreamCreateWithFlags(&s2, cudaStreamNonBlocking);
        cudaStreamCreateWithFlags(&s3, cudaStreamNonBlocking);
        cudaEventCreateWithFlags(&e0, cudaEventDisableTiming);
        cudaEventCreateWithFlags(&e2, cudaEventDisableTiming);
        cudaEventCreateWithFlags(&e3, cudaEventDisableTiming);
        cudaFuncSetAttribute(k_selpick, cudaFuncAttributeMaxDynamicSharedMemorySize, P_ * 4);
    }

    k_init<<<1, 256>>>();
    cudaEventRecord(e0, 0);
    cudaStreamWaitEvent(s2, e0, 0);
    cudaStreamWaitEvent(s3, e0, 0);

    // stream s2: matching chain
    dim3 gm(MBLK, B_);
    k_match<<<gm, 256, 0, s2>>>(priors, box_gt, class_gt);
    k_override<<<1, 32, 0, s2>>>(class_gt);
    cudaEventRecord(e2, s2);

    // stream s3: mask-GT fused resize
    k_resize<<<B_ * PH_, 256, 0, s3>>>(mask_gt);
    cudaEventRecord(e3, s3);

    // main stream: lse sweep (independent), then joins
    k_lse<<<(B_ * P_) / 8, 256>>>(class_p);
    cudaStreamWaitEvent(0, e2, 0);
    k_posloss<<<gm, 256>>>(class_p, box_p, priors, box_gt);
    k_selpick<<<16, 512, P_ * 4>>>();
    cudaStreamWaitEvent(0, e3, 0);
    dim3 gk(MTT_, B_);
    k_mask<<<gk, 256>>>(proto_p, coef_p, box_gt);
    k_final<<<1, 32>>>(out);
}

// round 6
// speedup vs baseline: 1.9403x; 1.2818x over previous
#include <cuda_runtime.h>
#include <math.h>

#define B_    8
#define P_    19248
#define C_    81
#define NOBJ_ 8
#define KC_   32
#define PH_   138
#define PW_   138
#define HH_   550
#define WW_   550
#define NPIX_ (PH_*PW_)
#define MTT_  100
#define SEG3  38   // ceil(P_/512)
#define MBLK  76   // ceil(P_/256)

// ------------------------- device scratch (static) -------------------------
__device__ double             g_acc[2];          // 0: box raw, 1: conf raw
__device__ double             g_mlsum[B_];       // pixel-part mask loss per batch
__device__ unsigned long long g_boxkey[B_][NOBJ_];
__device__ int                g_conf[B_][P_];
__device__ unsigned char      g_pmi[B_][P_];
__device__ float              g_mark[B_][P_];
__device__ float              g_lse[B_][P_];
__device__ int                g_numpos[B_];
__device__ unsigned char      g_dm[B_][NPIX_];
__device__ float              g_wts[PH_][9];
__device__ int                g_wi0[PH_];
__device__ int                g_ones[B_][NOBJ_];
__device__ int                g_sel[B_][MTT_];
__device__ int                g_selcnt[B_];
__device__ int4               g_rect[B_][MTT_];   // xlo,xhi,ylo,yhi
__device__ float              g_invd[B_][MTT_];
__device__ int                g_obit[B_][MTT_];

// ------------------------- reduce / scan helpers -------------------------
__device__ __forceinline__ float bRedF256(float v) {
    __shared__ float sd[8];
    int ln = threadIdx.x & 31, wd = threadIdx.x >> 5;
    #pragma unroll
    for (int o = 16; o; o >>= 1) v += __shfl_down_sync(0xffffffffu, v, o);
    if (ln == 0) sd[wd] = v;
    __syncthreads();
    v = (threadIdx.x < 8) ? sd[threadIdx.x] : 0.f;
    if (wd == 0) {
        #pragma unroll
        for (int o = 4; o; o >>= 1) v += __shfl_down_sync(0xffffffffu, v, o);
        if (ln == 0) sd[0] = v;
    }
    __syncthreads();
    float r = sd[0];
    __syncthreads();
    return r;
}
__device__ __forceinline__ float bRedF512(float v) {
    __shared__ float sd[16];
    int ln = threadIdx.x & 31, wd = threadIdx.x >> 5;
    #pragma unroll
    for (int o = 16; o; o >>= 1) v += __shfl_down_sync(0xffffffffu, v, o);
    if (ln == 0) sd[wd] = v;
    __syncthreads();
    v = (threadIdx.x < 16) ? sd[threadIdx.x] : 0.f;
    if (wd == 0) {
        #pragma unroll
        for (int o = 8; o; o >>= 1) v += __shfl_down_sync(0xffffffffu, v, o);
        if (ln == 0) sd[0] = v;
    }
    __syncthreads();
    float r = sd[0];
    __syncthreads();
    return r;
}
__device__ __forceinline__ int bRedI512(int v) {
    __shared__ int si[16];
    int ln = threadIdx.x & 31, wd = threadIdx.x >> 5;
    #pragma unroll
    for (int o = 16; o; o >>= 1) v += __shfl_down_sync(0xffffffffu, v, o);
    if (ln == 0) si[wd] = v;
    __syncthreads();
    v = (threadIdx.x < 16) ? si[threadIdx.x] : 0;
    if (wd == 0) {
        #pragma unroll
        for (int o = 8; o; o >>= 1) v += __shfl_down_sync(0xffffffffu, v, o);
        if (ln == 0) si[0] = v;
    }
    __syncthreads();
    int r = si[0];
    __syncthreads();
    return r;
}
__device__ __forceinline__ int bScanEx512(int v, int* sh) {
    int tid = threadIdx.x;
    sh[tid] = v;
    __syncthreads();
    #pragma unroll
    for (int off = 1; off < 512; off <<= 1) {
        int t = (tid >= off) ? sh[tid - off] : 0;
        __syncthreads();
        sh[tid] += t;
        __syncthreads();
    }
    int incl = sh[tid];
    __syncthreads();
    return incl - v;
}

// ------------------------- K0: init -------------------------
__global__ void k_init() {
    int t = threadIdx.x;
    if (t < PH_) {
        float inv = (float)(1.0 / (138.0 / 550.0));
        float s = ((float)t + 0.5f) * inv - 0.5f;
        int i0 = (int)ceilf(s - inv);
        int i1 = (int)floorf(s + inv);
        if (i0 < 0) i0 = 0;
        if (i1 > HH_ - 1) i1 = HH_ - 1;
        int cnt = i1 - i0 + 1; if (cnt > 9) cnt = 9;
        float w[9]; float wsum = 0.f;
        #pragma unroll
        for (int k = 0; k < 9; k++) {
            float x = __fdiv_rn(fabsf((float)(i0 + k) - s), inv);
            float wv = fmaxf(0.f, 1.f - x);
            if (k >= cnt) wv = 0.f;
            w[k] = wv; wsum += wv;
        }
        #pragma unroll
        for (int k = 0; k < 9; k++) g_wts[t][k] = __fdiv_rn(w[k], wsum);
        g_wi0[t] = i0;
    }
    if (t < B_ * NOBJ_) {
        ((unsigned long long*)g_boxkey)[t] = 0ull;
        ((int*)g_ones)[t] = 0;
    }
    if (t < B_) { g_numpos[t] = 0; g_mlsum[t] = 0.0; g_selcnt[t] = 0; }
    if (t < 2) g_acc[t] = 0.0;
}

// ------------------------- K1: matching -------------------------
__global__ void __launch_bounds__(256) k_match(const float* __restrict__ priors,
                                               const float* __restrict__ box_gt,
                                               const int* __restrict__ class_gt) {
    int b = blockIdx.y;
    int tid = threadIdx.x;
    int p = blockIdx.x * 256 + tid;
    bool valid = p < P_;
    int lane = tid & 31;
    __shared__ float sbg[NOBJ_][4];
    __shared__ unsigned long long skey[NOBJ_];
    if (tid < NOBJ_ * 4) ((float*)sbg)[tid] = box_gt[b * NOBJ_ * 4 + tid];
    if (tid < NOBJ_) skey[tid] = 0ull;
    __syncthreads();

    float dx1 = 0.f, dy1 = 0.f, dx2 = 0.f, dy2 = 0.f, areaP = 0.f;
    if (valid) {
        float4 pr = ((const float4*)priors)[p];
        float w2 = __fmul_rn(pr.z, 0.5f), h2 = __fmul_rn(pr.w, 0.5f);
        dx1 = __fsub_rn(pr.x, w2); dy1 = __fsub_rn(pr.y, h2);
        dx2 = __fadd_rn(pr.x, w2); dy2 = __fadd_rn(pr.y, h2);
        areaP = __fmul_rn(__fsub_rn(dx2, dx1), __fsub_rn(dy2, dy1));
    }
    float best = -1.f; int besto = 0;
    #pragma unroll
    for (int o = 0; o < NOBJ_; o++) {
        unsigned u = 0u;
        if (valid) {
            float gx1 = sbg[o][0], gy1 = sbg[o][1], gx2 = sbg[o][2], gy2 = sbg[o][3];
            float ix = fmaxf(__fsub_rn(fminf(gx2, dx2), fmaxf(gx1, dx1)), 0.f);
            float iy = fmaxf(__fsub_rn(fminf(gy2, dy2), fmaxf(gy1, dy1)), 0.f);
            float inter = __fmul_rn(ix, iy);
            float areaG = __fmul_rn(__fsub_rn(gx2, gx1), __fsub_rn(gy2, gy1));
            float iou = __fdiv_rn(inter, __fsub_rn(__fadd_rn(areaG, areaP), inter));
            if (iou > best) { best = iou; besto = o; }
            u = __float_as_uint(iou);
        }
        unsigned wmax = __reduce_max_sync(0xffffffffu, u);
        unsigned bal = __ballot_sync(0xffffffffu, u == wmax);
        int leader = __ffs(bal) - 1;
        if (lane == leader && valid)
            atomicMax(&skey[o], (((unsigned long long)u) << 32)
                               | (unsigned long long)(0xFFFFFFFFu - (unsigned)p));
    }
    if (valid) {
        int cg = class_gt[b * NOBJ_ + besto];
        int cf = cg + 1;
        if (best < 0.5f) cf = -1;
        if (best < 0.4f) cf = 0;
        g_conf[b][p] = cf;
        g_pmi[b][p]  = (unsigned char)besto;
    }
    __syncthreads();
    if (tid < NOBJ_ && skey[tid]) atomicMax(&g_boxkey[b][tid], skey[tid]);
}

// ------------------------- K1b: forced matches -------------------------
__global__ void k_override(const int* __restrict__ class_gt) {
    int b = threadIdx.x;
    if (b < B_) {
        for (int o = 0; o < NOBJ_; o++) {
            unsigned long long k = g_boxkey[b][o];
            unsigned p = 0xFFFFFFFFu - (unsigned)(k & 0xFFFFFFFFull);
            g_conf[b][p] = class_gt[b * NOBJ_ + o] + 1;
            g_pmi[b][p]  = (unsigned char)o;
        }
    }
}

// ------------------------- K2: lse/mark sweep -------------------------
__global__ void __launch_bounds__(256) k_lse(const float* __restrict__ class_p) {
    int gw = blockIdx.x * 8 + (threadIdx.x >> 5);
    int lane = threadIdx.x & 31;
    const float* xp = class_p + (size_t)gw * C_;
    float v0 = xp[lane];
    float v1 = xp[lane + 32];
    float v2 = (lane < C_ - 64) ? xp[lane + 64] : 0.f;
    float s = __expf(v0) + __expf(v1);
    if (lane < C_ - 64) s += __expf(v2);
    #pragma unroll
    for (int off = 16; off; off >>= 1) s += __shfl_xor_sync(0xffffffffu, s, off);
    float lse = __logf(s);
    float x0 = __shfl_sync(0xffffffffu, v0, 0);
    if (lane == 0) {
        int b = gw / P_, p = gw % P_;
        g_lse[b][p]  = lse;
        g_mark[b][p] = lse - x0;
    }
}

// ------------------------- K3: positive losses + numpos -------------------------
__global__ void __launch_bounds__(256) k_posloss(const float* __restrict__ class_p,
                                                 const float* __restrict__ box_p,
                                                 const float* __restrict__ priors,
                                                 const float* __restrict__ box_gt) {
    int b = blockIdx.y;
    int p = blockIdx.x * 256 + threadIdx.x;
    int lane = threadIdx.x & 31;
    bool pos = false;
    int cf = 0;
    if (p < P_) { cf = g_conf[b][p]; pos = cf > 0; }

    float lb = 0.f, nll = 0.f;
    if (pos) {
        float lse = g_lse[b][p];
        float xt = class_p[((size_t)(b * P_ + p)) * C_ + cf];
        nll = lse - xt;
        int o = g_pmi[b][p];
        const float* bg = box_gt + (size_t)(b * NOBJ_ + o) * 4;
        float mnx = bg[0], mny = bg[1], mxx = bg[2], mxy = bg[3];
        float4 pr = ((const float4*)priors)[p];
        float off0 = __fdiv_rn(__fsub_rn(__fmul_rn(__fadd_rn(mnx, mxx), 0.5f), pr.x), __fmul_rn(0.1f, pr.z));
        float off1 = __fdiv_rn(__fsub_rn(__fmul_rn(__fadd_rn(mny, mxy), 0.5f), pr.y), __fmul_rn(0.1f, pr.w));
        float off2 = __fdiv_rn(logf(__fdiv_rn(__fsub_rn(mxx, mnx), pr.z)), 0.2f);
        float off3 = __fdiv_rn(logf(__fdiv_rn(__fsub_rn(mxy, mny), pr.w)), 0.2f);
        const float4 bp = ((const float4*)box_p)[b * P_ + p];
        float d;
        d = fabsf(bp.x - off0); lb += (d < 1.f) ? 0.5f*d*d : d - 0.5f;
        d = fabsf(bp.y - off1); lb += (d < 1.f) ? 0.5f*d*d : d - 0.5f;
        d = fabsf(bp.z - off2); lb += (d < 1.f) ? 0.5f*d*d : d - 0.5f;
        d = fabsf(bp.w - off3); lb += (d < 1.f) ? 0.5f*d*d : d - 0.5f;
    }
    unsigned bal = __ballot_sync(0xffffffffu, pos);
    #pragma unroll
    for (int off = 16; off; off >>= 1) {
        lb  += __shfl_down_sync(0xffffffffu, lb, off);
        nll += __shfl_down_sync(0xffffffffu, nll, off);
    }
    if (lane == 0 && bal) {
        atomicAdd(&g_numpos[b], __popc(bal));
        atomicAdd(&g_acc[0], (double)lb);
        atomicAdd(&g_acc[1], (double)nll);
    }
}

// ------------------------- K4: select (8 blocks) + pick+meta (8 blocks) -------------------------
__global__ void __launch_bounds__(512) k_selpick(const float* __restrict__ box_gt) {
    extern __shared__ float smk[];
    __shared__ int hist[256];
    __shared__ int sscan[512];
    __shared__ unsigned sh_prefix;
    __shared__ int sh_rem;
    int tid = threadIdx.x;

    if (blockIdx.x < 8) {
        int b = blockIdx.x;
        int np = g_numpos[b];
        long long kll = 3LL * np; if (kll > P_ - 1) kll = P_ - 1;
        if (kll <= 0) return;
        for (int p = tid; p < P_; p += 512) {
            float v = (g_conf[b][p] == 0) ? g_mark[b][p] : 0.f;
            smk[p] = v;
        }
        if (tid == 0) { sh_prefix = 0u; sh_rem = (int)kll; }
        __syncthreads();

        for (int pass = 0; pass < 4; pass++) {
            int shift = 24 - 8 * pass;
            unsigned himask = (pass == 0) ? 0u : (0xFFFFFFFFu << (shift + 8));
            if (tid < 256) hist[tid] = 0;
            __syncthreads();
            unsigned pref = sh_prefix;
            for (int p = tid; p < P_; p += 512) {
                unsigned u = __float_as_uint(smk[p]);
                if ((u & himask) == pref)
                    atomicAdd(&hist[(u >> shift) & 255], 1);
            }
            __syncthreads();
            if (tid == 0) {
                int rem = sh_rem;
                int cum = 0, bin = 255;
                for (; bin > 0; bin--) {
                    cum += hist[bin];
                    if (cum >= rem) break;
                }
                if (cum < rem) cum += hist[0];
                sh_rem = rem - (cum - hist[bin]);
                sh_prefix = pref | ((unsigned)bin << shift);
            }
            __syncthreads();
        }
        unsigned tb = sh_prefix;
        int quota = sh_rem;

        float sgt = 0.f, seq = 0.f; int ceq = 0;
        for (int p = tid; p < P_; p += 512) {
            float v = smk[p];
            unsigned u = __float_as_uint(v);
            if (u > tb) sgt += v;
            else if (u == tb) { seq += v; ceq++; }
        }
        float sgt_t = bRedF512(sgt);
        float seq_t = bRedF512(seq);
        int   ceq_t = bRedI512(ceq);
        bool ordered = (ceq_t != quota) && (tb != 0u);
        if (tid == 0) atomicAdd(&g_acc[1], (double)(sgt_t + (ordered ? 0.f : seq_t)));

        if (ordered) {
            int s0 = tid * SEG3, s1 = s0 + SEG3; if (s1 > P_) s1 = P_;
            int c = 0;
            for (int p = s0; p < s1; p++)
                if (__float_as_uint(smk[p]) == tb) c++;
            int pre = bScanEx512(c, sscan);
            float sord = 0.f; int r = pre;
            for (int p = s0; p < s1; p++) {
                if (__float_as_uint(smk[p]) == tb) {
                    if (r < quota) sord += smk[p];
                    r++;
                }
            }
            float st = bRedF512(sord);
            if (tid == 0) atomicAdd(&g_acc[1], (double)st);
        }
    } else {
        int b = blockIdx.x - 8;
        int np = g_numpos[b];
        int cap = np < MTT_ ? np : MTT_;
        if (tid == 0) g_selcnt[b] = cap;
        int s0 = tid * SEG3, s1 = s0 + SEG3; if (s1 > P_) s1 = P_;
        int c = 0;
        for (int p = s0; p < s1; p++)
            if (g_conf[b][p] > 0) c++;
        int pre = bScanEx512(c, sscan);
        int r = pre;
        for (int p = s0; p < s1; p++) {
            if (g_conf[b][p] > 0) {
                if (r < cap) g_sel[b][r] = p;
                r++;
            }
        }
        __syncthreads();
        // metadata for each selected mask
        for (int k = tid; k < cap; k += 512) {
            int p = g_sel[b][k];
            int o = g_pmi[b][p];
            const float* bg = box_gt + (size_t)(b * NOBJ_ + o) * 4;
            float bx1 = bg[0], by1 = bg[1], bx2 = bg[2], by2 = bg[3];
            float ax = bx1 * 138.f, bx = bx2 * 138.f;
            float x1 = fminf(ax, bx), x2 = fmaxf(ax, bx);
            x1 = fmaxf(x1 - 1.f, 0.f); x2 = fminf(x2 + 1.f, 138.f);
            float ay = by1 * 138.f, by = by2 * 138.f;
            float y1 = fminf(ay, by), y2 = fmaxf(ay, by);
            y1 = fmaxf(y1 - 1.f, 0.f); y2 = fminf(y2 + 1.f, 138.f);
            int xlo = (int)ceilf(x1), xhi = (int)ceilf(x2);
            int ylo = (int)ceilf(y1), yhi = (int)ceilf(y2);
            if (xlo < 0) xlo = 0; if (xhi > PW_) xhi = PW_;
            if (ylo < 0) ylo = 0; if (yhi > PH_) yhi = PH_;
            int4 r4; r4.x = xlo; r4.y = xhi; r4.z = ylo; r4.w = yhi;
            g_rect[b][k] = r4;
            double denom = (double)((bx2 - bx1) * (by2 - by1));
            g_invd[b][k] = (float)(1.0 / denom);
            g_obit[b][k] = o;
        }
    }
}

// ------------------------- K5: fused resize, warp-per-object, float2 -------------------------
__global__ void __launch_bounds__(256) k_resize(const float* __restrict__ mg) {
    __shared__ float srow[NOBJ_][WW_];
    __shared__ int shc[NOBJ_];
    int b  = blockIdx.x / PH_;
    int yo = blockIdx.x % PH_;
    int tid = threadIdx.x;
    int w   = tid >> 5;      // warp = object
    int lane = tid & 31;
    int i0 = g_wi0[yo];
    float wy[9];
    #pragma unroll
    for (int t = 0; t < 9; t++) wy[t] = g_wts[yo][t];
    if (tid < NOBJ_) shc[tid] = 0;

    const float* src = mg + ((size_t)(b * NOBJ_ + w)) * HH_ * WW_;
    const float2* rows2[9];
    #pragma unroll
    for (int t = 0; t < 9; t++) {
        int yi = i0 + t; if (yi > HH_ - 1) yi = HH_ - 1;
        rows2[t] = (const float2*)(src + (size_t)yi * WW_);
    }
    float2* drow = (float2*)&srow[w][0];
    for (int c = lane; c < WW_ / 2; c += 32) {
        float ax = 0.f, ay = 0.f;
        #pragma unroll
        for (int t = 0; t < 9; t++) {
            float2 v = rows2[t][c];
            ax += wy[t] * v.x;
            ay += wy[t] * v.y;
        }
        float2 o2; o2.x = ax; o2.y = ay;
        drow[c] = o2;
    }
    __syncthreads();

    unsigned bits = 0;
    if (tid < PW_) {
        int j0 = g_wi0[tid];
        float wx[9];
        #pragma unroll
        for (int t = 0; t < 9; t++) wx[t] = g_wts[tid][t];
        #pragma unroll
        for (int o = 0; o < NOBJ_; o++) {
            float s = 0.f;
            #pragma unroll
            for (int t = 0; t < 9; t++) {
                int xi = j0 + t; if (xi > WW_ - 1) xi = WW_ - 1;
                s += wx[t] * srow[o][xi];
            }
            if (s > 0.5f) bits |= (1u << o);
        }
        g_dm[b][yo * PW_ + tid] = (unsigned char)bits;
    }
    int lane2 = tid & 31;
    #pragma unroll
    for (int o = 0; o < NOBJ_; o++) {
        unsigned mb = __ballot_sync(0xffffffffu, (bits >> o) & 1);
        if (lane2 == 0 && mb) atomicAdd(&shc[o], __popc(mb));
    }
    __syncthreads();
    if (tid < NOBJ_ && shc[tid]) atomicAdd(&g_ones[b][tid], shc[tid]);
}

// ------------------------- K6: mask BCE, pixel-centric -------------------------
__global__ void __launch_bounds__(256) k_mask(const float* __restrict__ proto_p,
                                              const float* __restrict__ coef_p) {
    __shared__ float4 scoef[MTT_][8];
    __shared__ int4   srect[MTT_];
    __shared__ float  sinv[MTT_];
    __shared__ int    sob[MTT_];
    int b = blockIdx.y;
    int tid = threadIdx.x;
    int px = blockIdx.x * 256 + tid;
    int cnt = g_selcnt[b];

    for (int i = tid; i < cnt * 8; i += 256) {
        int k = i >> 3, q = i & 7;
        int p = g_sel[b][k];
        scoef[k][q] = ((const float4*)(coef_p + ((size_t)(b * P_ + p)) * KC_))[q];
    }
    for (int i = tid; i < cnt; i += 256) {
        srect[i] = g_rect[b][i];
        sinv[i]  = g_invd[b][i];
        sob[i]   = g_obit[b][i];
    }
    __syncthreads();

    float acc = 0.f;
    if (px < NPIX_ && cnt > 0) {
        int y = px / PW_, x = px % PW_;
        const float4* pp = (const float4*)(proto_p + (size_t)(b * NPIX_ + px) * KC_);
        float4 r0 = pp[0], r1 = pp[1], r2 = pp[2], r3 = pp[3];
        float4 r4 = pp[4], r5 = pp[5], r6 = pp[6], r7 = pp[7];
        unsigned dmb = g_dm[b][px];
        const float L = 16.118095651f;
        const float A  = -logf(1e-7f);
        const float Bc = -log1pf(-1e-7f);
        for (int k = 0; k < cnt; k++) {
            int4 r = srect[k];
            if (x >= r.x && x < r.y && y >= r.z && y < r.w) {
                const float4* ck = scoef[k];
                float4 c0 = ck[0], c1 = ck[1], c2 = ck[2], c3 = ck[3];
                float4 c4 = ck[4], c5 = ck[5], c6 = ck[6], c7 = ck[7];
                float z =
                    r0.x*c0.x + r0.y*c0.y + r0.z*c0.z + r0.w*c0.w +
                    r1.x*c1.x + r1.y*c1.y + r1.z*c1.z + r1.w*c1.w +
                    r2.x*c2.x + r2.y*c2.y + r2.z*c2.z + r2.w*c2.w +
                    r3.x*c3.x + r3.y*c3.y + r3.z*c3.z + r3.w*c3.w +
                    r4.x*c4.x + r4.y*c4.y + r4.z*c4.z + r4.w*c4.w +
                    r5.x*c5.x + r5.y*c5.y + r5.z*c5.z + r5.w*c5.w +
                    r6.x*c6.x + r6.y*c6.y + r6.z*c6.z + r6.w*c6.w +
                    r7.x*c7.x + r7.y*c7.y + r7.z*c7.z + r7.w*c7.w;
                float zc = fminf(fmaxf(z, -L), L);
                float sp = fmaxf(zc, 0.f) + __logf(1.f + __expf(-fabsf(zc)));
                int gt = (dmb >> sob[k]) & 1;
                float vp = sp - (gt ? (zc + A) : Bc);
                acc += vp * sinv[k];
            }
        }
    }
    float t = bRedF256(acc);
    if (tid == 0) atomicAdd(&g_mlsum[b], (double)t);
}

// ------------------------- K7: final combine (parallel constant part) -------------------------
__global__ void __launch_bounds__(256) k_final(float* out) {
    __shared__ double sd[8];
    int tid = threadIdx.x;
    const float A  = -logf(1e-7f);
    const float Bc = -log1pf(-1e-7f);
    double acc = 0.0;
    for (int i = tid; i < B_ * MTT_; i += 256) {
        int b = i / MTT_, k = i % MTT_;
        if (k < g_selcnt[b]) {
            int o = g_obit[b][k];
            int ones = g_ones[b][o];
            double c = (double)ones * (double)A + (double)(NPIX_ - ones) * (double)Bc;
            int np = g_numpos[b];
            double s = 1.0;
            if (np > MTT_) {
                float npf = (float)np;
                s = (double)(npf / fmaxf(fminf(npf, (float)MTT_), 1.f));
            }
            acc += c * (double)g_invd[b][k] * s;
        }
    }
    if (tid < B_) {
        int np = g_numpos[tid];
        double s = 1.0;
        if (np > MTT_) {
            float npf = (float)np;
            s = (double)(npf / fmaxf(fminf(npf, (float)MTT_), 1.f));
        }
        acc += g_mlsum[tid] * s;
    }
    int ln = tid & 31, wd = tid >> 5;
    #pragma unroll
    for (int o = 16; o; o >>= 1) acc += __shfl_down_sync(0xffffffffu, acc, o);
    if (ln == 0) sd[wd] = acc;
    __syncthreads();
    if (tid < 8) {
        acc = sd[tid];
        #pragma unroll
        for (int o = 4; o; o >>= 1) acc += __shfl_down_sync(0xffffffffu, acc, o);
        if (tid == 0) {
            double total = 1.5 * g_acc[0] + g_acc[1] + acc * 6.125 / 138.0 / 138.0;
            out[0] = (float)total;
        }
    }
}

// ------------------------- launch (3-stream fork/join) -------------------------
extern "C" void kernel_launch(void* const* d_in, const int* in_sizes, int n_in,
                              void* d_out, int out_size) {
    const float* class_p  = (const float*)d_in[0];
    const float* box_p    = (const float*)d_in[1];
    const float* coef_p   = (const float*)d_in[2];
    const float* proto_p  = (const float*)d_in[3];
    const float* priors   = (const float*)d_in[4];
    const float* box_gt   = (const float*)d_in[5];
    const float* mask_gt  = (const float*)d_in[6];
    const int*   class_gt = (const int*)d_in[7];
    float* out = (float*)d_out;

    static cudaStream_t s2 = nullptr, s3 = nullptr;
    static cudaEvent_t  e0 = nullptr, e2 = nullptr, e3 = nullptr;
    if (!s2) {
        cudaStreamCreateWithFlags(&s2, cudaStreamNonBlocking);
        cudaStreamCreateWithFlags(&s3, cudaStreamNonBlocking);
        cudaEventCreateWithFlags(&e0, cudaEventDisableTiming);
        cudaEventCreateWithFlags(&e2, cudaEventDisableTiming);
        cudaEventCreateWithFlags(&e3, cudaEventDisableTiming);
        cudaFuncSetAttribute(k_selpick, cudaFuncAttributeMaxDynamicSharedMemorySize, P_ * 4);
    }

    k_init<<<1, 256>>>();
    cudaEventRecord(e0, 0);
    cudaStreamWaitEvent(s2, e0, 0);
    cudaStreamWaitEvent(s3, e0, 0);

    // stream s2: matching chain
    dim3 gm(MBLK, B_);
    k_match<<<gm, 256, 0, s2>>>(priors, box_gt, class_gt);
    k_override<<<1, 32, 0, s2>>>(class_gt);
    cudaEventRecord(e2, s2);

    // stream s3: mask-GT fused resize
    k_resize<<<B_ * PH_, 256, 0, s3>>>(mask_gt);
    cudaEventRecord(e3, s3);

    // main stream
    k_lse<<<(B_ * P_) / 8, 256>>>(class_p);
    cudaStreamWaitEvent(0, e2, 0);
    k_posloss<<<gm, 256>>>(class_p, box_p, priors, box_gt);
    k_selpick<<<16, 512, P_ * 4>>>(box_gt);
    cudaStreamWaitEvent(0, e3, 0);
    dim3 gk((NPIX_ + 255) / 256, B_);
    k_mask<<<gk, 256>>>(proto_p, coef_p);
    k_final<<<1, 256>>>(out);
}

// round 8
// speedup vs baseline: 1.9600x; 1.0101x over previous
#include <cuda_runtime.h>
#include <math.h>

#define B_    8
#define P_    19248
#define C_    81
#define NOBJ_ 8
#define KC_   32
#define PH_   138
#define PW_   138
#define HH_   550
#define WW_   550
#define NPIX_ (PH_*PW_)
#define MTT_  100
#define SEG3  38   // ceil(P_/512)
#define MBLK  76   // ceil(P_/256)

#define RES_BLOCKS   (B_*PH_)                 // 1104
#define MATCH_BLOCKS (B_*MBLK)                // 608
#define LSE_BLOCKS   ((B_*P_)/8)              // 19248
#define BIG_BLOCKS   (RES_BLOCKS + MATCH_BLOCKS + LSE_BLOCKS)

// ------------------------- device scratch (static) -------------------------
__device__ double             g_acc[2];
__device__ double             g_mlsum[B_];
__device__ unsigned long long g_boxkey[B_][NOBJ_];
__device__ int                g_conf[B_][P_];
__device__ unsigned char      g_pmi[B_][P_];
__device__ float              g_mark[B_][P_];
__device__ float              g_lse[B_][P_];
__device__ int                g_numpos[B_];
__device__ unsigned char      g_dm[B_][NPIX_];
__device__ float              g_wts[PH_][9];
__device__ int                g_wi0[PH_];
__device__ int                g_ones[B_][NOBJ_];
__device__ int                g_sel[B_][MTT_];
__device__ int                g_selcnt[B_];
__device__ int4               g_rect[B_][MTT_];
__device__ float              g_invd[B_][MTT_];
__device__ int                g_obit[B_][MTT_];

// ------------------------- helpers -------------------------
__device__ __forceinline__ float bRedF256(float v) {
    __shared__ float sd[8];
    int ln = threadIdx.x & 31, wd = threadIdx.x >> 5;
    #pragma unroll
    for (int o = 16; o; o >>= 1) v += __shfl_down_sync(0xffffffffu, v, o);
    if (ln == 0) sd[wd] = v;
    __syncthreads();
    v = (threadIdx.x < 8) ? sd[threadIdx.x] : 0.f;
    if (wd == 0) {
        #pragma unroll
        for (int o = 4; o; o >>= 1) v += __shfl_down_sync(0xffffffffu, v, o);
        if (ln == 0) sd[0] = v;
    }
    __syncthreads();
    float r = sd[0];
    __syncthreads();
    return r;
}
__device__ __forceinline__ float bRedF512(float v) {
    __shared__ float sd[16];
    int ln = threadIdx.x & 31, wd = threadIdx.x >> 5;
    #pragma unroll
    for (int o = 16; o; o >>= 1) v += __shfl_down_sync(0xffffffffu, v, o);
    if (ln == 0) sd[wd] = v;
    __syncthreads();
    v = (threadIdx.x < 16) ? sd[threadIdx.x] : 0.f;
    if (wd == 0) {
        #pragma unroll
        for (int o = 8; o; o >>= 1) v += __shfl_down_sync(0xffffffffu, v, o);
        if (ln == 0) sd[0] = v;
    }
    __syncthreads();
    float r = sd[0];
    __syncthreads();
    return r;
}
__device__ __forceinline__ int bRedI512(int v) {
    __shared__ int si[16];
    int ln = threadIdx.x & 31, wd = threadIdx.x >> 5;
    #pragma unroll
    for (int o = 16; o; o >>= 1) v += __shfl_down_sync(0xffffffffu, v, o);
    if (ln == 0) si[wd] = v;
    __syncthreads();
    v = (threadIdx.x < 16) ? si[threadIdx.x] : 0;
    if (wd == 0) {
        #pragma unroll
        for (int o = 8; o; o >>= 1) v += __shfl_down_sync(0xffffffffu, v, o);
        if (ln == 0) si[0] = v;
    }
    __syncthreads();
    int r = si[0];
    __syncthreads();
    return r;
}
__device__ __forceinline__ int bScanEx512(int v, int* sh) {
    int tid = threadIdx.x;
    sh[tid] = v;
    __syncthreads();
    #pragma unroll
    for (int off = 1; off < 512; off <<= 1) {
        int t = (tid >= off) ? sh[tid - off] : 0;
        __syncthreads();
        sh[tid] += t;
        __syncthreads();
    }
    int incl = sh[tid];
    __syncthreads();
    return incl - v;
}

// ------------------------- K0: init (weights + zero accumulators) -------------------------
__global__ void k_init() {
    int t = threadIdx.x;
    if (t < PH_) {
        float inv = (float)(1.0 / (138.0 / 550.0));
        float s = ((float)t + 0.5f) * inv - 0.5f;
        int i0 = (int)ceilf(s - inv);
        int i1 = (int)floorf(s + inv);
        if (i0 < 0) i0 = 0;
        if (i1 > HH_ - 1) i1 = HH_ - 1;
        int cnt = i1 - i0 + 1; if (cnt > 9) cnt = 9;
        float w[9]; float wsum = 0.f;
        #pragma unroll
        for (int k = 0; k < 9; k++) {
            float x = __fdiv_rn(fabsf((float)(i0 + k) - s), inv);
            float wv = fmaxf(0.f, 1.f - x);
            if (k >= cnt) wv = 0.f;
            w[k] = wv; wsum += wv;
        }
        #pragma unroll
        for (int k = 0; k < 9; k++) g_wts[t][k] = __fdiv_rn(w[k], wsum);
        g_wi0[t] = i0;
    }
    if (t < B_ * NOBJ_) {
        ((unsigned long long*)g_boxkey)[t] = 0ull;
        ((int*)g_ones)[t] = 0;
    }
    if (t < B_) { g_numpos[t] = 0; g_mlsum[t] = 0.0; g_selcnt[t] = 0; }
    if (t < 2) g_acc[t] = 0.0;
}

// ------------------------- K1: fused resize + match + lse -------------------------
__global__ void __launch_bounds__(256) k_big(const float* __restrict__ mg,
                                             const float* __restrict__ priors,
                                             const float* __restrict__ box_gt,
                                             const int* __restrict__ class_gt,
                                             const float* __restrict__ class_p) {
    int blk = blockIdx.x;
    int tid = threadIdx.x;
    if (blk < RES_BLOCKS) {
        // ================= resize role (round-5 proven body) =================
        __shared__ float srow[NOBJ_][WW_];
        __shared__ int shc[NOBJ_];
        int b  = blk / PH_;
        int yo = blk % PH_;
        int w  = tid >> 5;
        int lane = tid & 31;
        int i0 = g_wi0[yo];
        float wy[9];
        #pragma unroll
        for (int t = 0; t < 9; t++) wy[t] = g_wts[yo][t];
        if (tid < NOBJ_) shc[tid] = 0;

        const float* src = mg + ((size_t)(b * NOBJ_ + w)) * HH_ * WW_;
        const float2* rows2[9];
        #pragma unroll
        for (int t = 0; t < 9; t++) {
            int yi = i0 + t; if (yi > HH_ - 1) yi = HH_ - 1;
            rows2[t] = (const float2*)(src + (size_t)yi * WW_);
        }
        float2* drow = (float2*)&srow[w][0];
        #pragma unroll 2
        for (int c = lane; c < WW_ / 2; c += 32) {
            float ax = 0.f, ay = 0.f;
            #pragma unroll
            for (int t = 0; t < 9; t++) {
                float2 v = rows2[t][c];
                ax += wy[t] * v.x;
                ay += wy[t] * v.y;
            }
            float2 o2; o2.x = ax; o2.y = ay;
            drow[c] = o2;
        }
        __syncthreads();

        unsigned bits = 0;
        if (tid < PW_) {
            int j0 = g_wi0[tid];
            float wx[9];
            #pragma unroll
            for (int t = 0; t < 9; t++) wx[t] = g_wts[tid][t];
            #pragma unroll
            for (int o = 0; o < NOBJ_; o++) {
                float s = 0.f;
                #pragma unroll
                for (int t = 0; t < 9; t++) {
                    int xi = j0 + t; if (xi > WW_ - 1) xi = WW_ - 1;
                    s += wx[t] * srow[o][xi];
                }
                if (s > 0.5f) bits |= (1u << o);
            }
            g_dm[b][yo * PW_ + tid] = (unsigned char)bits;
        }
        #pragma unroll
        for (int o = 0; o < NOBJ_; o++) {
            unsigned mb = __ballot_sync(0xffffffffu, (bits >> o) & 1);
            if (lane == 0 && mb) atomicAdd(&shc[o], __popc(mb));
        }
        __syncthreads();
        if (tid < NOBJ_ && shc[tid]) atomicAdd(&g_ones[b][tid], shc[tid]);
    } else if (blk < RES_BLOCKS + MATCH_BLOCKS) {
        // ================= match role (round-5 proven body) =================
        int id = blk - RES_BLOCKS;
        int b = id / MBLK;
        int p = (id % MBLK) * 256 + tid;
        bool valid = p < P_;
        int lane = tid & 31;
        __shared__ float sbg[NOBJ_][4];
        __shared__ unsigned long long skey[NOBJ_];
        if (tid < NOBJ_ * 4) ((float*)sbg)[tid] = box_gt[b * NOBJ_ * 4 + tid];
        if (tid < NOBJ_) skey[tid] = 0ull;
        __syncthreads();

        float dx1 = 0.f, dy1 = 0.f, dx2 = 0.f, dy2 = 0.f, areaP = 0.f;
        if (valid) {
            float4 pr = ((const float4*)priors)[p];
            float w2 = __fmul_rn(pr.z, 0.5f), h2 = __fmul_rn(pr.w, 0.5f);
            dx1 = __fsub_rn(pr.x, w2); dy1 = __fsub_rn(pr.y, h2);
            dx2 = __fadd_rn(pr.x, w2); dy2 = __fadd_rn(pr.y, h2);
            areaP = __fmul_rn(__fsub_rn(dx2, dx1), __fsub_rn(dy2, dy1));
        }
        float best = -1.f; int besto = 0;
        #pragma unroll
        for (int o = 0; o < NOBJ_; o++) {
            unsigned u = 0u;
            if (valid) {
                float gx1 = sbg[o][0], gy1 = sbg[o][1], gx2 = sbg[o][2], gy2 = sbg[o][3];
                float ix = fmaxf(__fsub_rn(fminf(gx2, dx2), fmaxf(gx1, dx1)), 0.f);
                float iy = fmaxf(__fsub_rn(fminf(gy2, dy2), fmaxf(gy1, dy1)), 0.f);
                float inter = __fmul_rn(ix, iy);
                float areaG = __fmul_rn(__fsub_rn(gx2, gx1), __fsub_rn(gy2, gy1));
                float iou = __fdiv_rn(inter, __fsub_rn(__fadd_rn(areaG, areaP), inter));
                if (iou > best) { best = iou; besto = o; }
                u = __float_as_uint(iou);
            }
            unsigned wmax = __reduce_max_sync(0xffffffffu, u);
            unsigned bal = __ballot_sync(0xffffffffu, u == wmax);
            int leader = __ffs(bal) - 1;
            if (lane == leader && valid)
                atomicMax(&skey[o], (((unsigned long long)u) << 32)
                                   | (unsigned long long)(0xFFFFFFFFu - (unsigned)p));
        }
        if (valid) {
            int cg = class_gt[b * NOBJ_ + besto];
            int cf = cg + 1;
            if (best < 0.5f) cf = -1;
            if (best < 0.4f) cf = 0;
            g_conf[b][p] = cf;
            g_pmi[b][p]  = (unsigned char)besto;
        }
        __syncthreads();
        if (tid < NOBJ_ && skey[tid]) atomicMax(&g_boxkey[b][tid], skey[tid]);
    } else {
        // ================= lse role (round-5 proven body) =================
        int gw = (blk - RES_BLOCKS - MATCH_BLOCKS) * 8 + (tid >> 5);
        int lane = tid & 31;
        const float* xp = class_p + (size_t)gw * C_;
        float v0 = xp[lane];
        float v1 = xp[lane + 32];
        float v2 = (lane < C_ - 64) ? xp[lane + 64] : 0.f;
        float s = __expf(v0) + __expf(v1);
        if (lane < C_ - 64) s += __expf(v2);
        #pragma unroll
        for (int off = 16; off; off >>= 1) s += __shfl_xor_sync(0xffffffffu, s, off);
        float lse = __logf(s);
        float x0 = __shfl_sync(0xffffffffu, v0, 0);
        if (lane == 0) {
            int b = gw / P_, p = gw % P_;
            g_lse[b][p]  = lse;
            g_mark[b][p] = lse - x0;
        }
    }
}

// ------------------------- K2: forced matches -------------------------
__global__ void k_override(const int* __restrict__ class_gt) {
    int b = threadIdx.x;
    if (b < B_) {
        for (int o = 0; o < NOBJ_; o++) {
            unsigned long long k = g_boxkey[b][o];
            unsigned p = 0xFFFFFFFFu - (unsigned)(k & 0xFFFFFFFFull);
            g_conf[b][p] = class_gt[b * NOBJ_ + o] + 1;
            g_pmi[b][p]  = (unsigned char)o;
        }
    }
}

// ------------------------- K3: positive losses + numpos -------------------------
__global__ void __launch_bounds__(256) k_posloss(const float* __restrict__ class_p,
                                                 const float* __restrict__ box_p,
                                                 const float* __restrict__ priors,
                                                 const float* __restrict__ box_gt) {
    int b = blockIdx.y;
    int p = blockIdx.x * 256 + threadIdx.x;
    int lane = threadIdx.x & 31;
    bool pos = false;
    int cf = 0;
    if (p < P_) { cf = g_conf[b][p]; pos = cf > 0; }

    float lb = 0.f, nll = 0.f;
    if (pos) {
        float lse = g_lse[b][p];
        float xt = class_p[((size_t)(b * P_ + p)) * C_ + cf];
        nll = lse - xt;
        int o = g_pmi[b][p];
        const float* bg = box_gt + (size_t)(b * NOBJ_ + o) * 4;
        float mnx = bg[0], mny = bg[1], mxx = bg[2], mxy = bg[3];
        float4 pr = ((const float4*)priors)[p];
        float off0 = __fdiv_rn(__fsub_rn(__fmul_rn(__fadd_rn(mnx, mxx), 0.5f), pr.x), __fmul_rn(0.1f, pr.z));
        float off1 = __fdiv_rn(__fsub_rn(__fmul_rn(__fadd_rn(mny, mxy), 0.5f), pr.y), __fmul_rn(0.1f, pr.w));
        float off2 = __fdiv_rn(logf(__fdiv_rn(__fsub_rn(mxx, mnx), pr.z)), 0.2f);
        float off3 = __fdiv_rn(logf(__fdiv_rn(__fsub_rn(mxy, mny), pr.w)), 0.2f);
        const float4 bp = ((const float4*)box_p)[b * P_ + p];
        float d;
        d = fabsf(bp.x - off0); lb += (d < 1.f) ? 0.5f*d*d : d - 0.5f;
        d = fabsf(bp.y - off1); lb += (d < 1.f) ? 0.5f*d*d : d - 0.5f;
        d = fabsf(bp.z - off2); lb += (d < 1.f) ? 0.5f*d*d : d - 0.5f;
        d = fabsf(bp.w - off3); lb += (d < 1.f) ? 0.5f*d*d : d - 0.5f;
    }
    unsigned bal = __ballot_sync(0xffffffffu, pos);
    #pragma unroll
    for (int off = 16; off; off >>= 1) {
        lb  += __shfl_down_sync(0xffffffffu, lb, off);
        nll += __shfl_down_sync(0xffffffffu, nll, off);
    }
    if (lane == 0 && bal) {
        atomicAdd(&g_numpos[b], __popc(bal));
        atomicAdd(&g_acc[0], (double)lb);
        atomicAdd(&g_acc[1], (double)nll);
    }
}

// ------------------------- K4: select + pick + meta -------------------------
__global__ void __launch_bounds__(512) k_selpick(const float* __restrict__ box_gt) {
    extern __shared__ float smk[];
    __shared__ int hist[256];
    __shared__ int sscan[512];
    __shared__ unsigned sh_prefix;
    __shared__ int sh_rem;
    int tid = threadIdx.x;

    if (blockIdx.x < 8) {
        int b = blockIdx.x;
        int np = g_numpos[b];
        long long kll = 3LL * np; if (kll > P_ - 1) kll = P_ - 1;
        if (kll <= 0) return;
        for (int p = tid; p < P_; p += 512) {
            float v = (g_conf[b][p] == 0) ? g_mark[b][p] : 0.f;
            smk[p] = v;
        }
        if (tid == 0) { sh_prefix = 0u; sh_rem = (int)kll; }
        __syncthreads();

        for (int pass = 0; pass < 4; pass++) {
            int shift = 24 - 8 * pass;
            unsigned himask = (pass == 0) ? 0u : (0xFFFFFFFFu << (shift + 8));
            if (tid < 256) hist[tid] = 0;
            __syncthreads();
            unsigned pref = sh_prefix;
            for (int p = tid; p < P_; p += 512) {
                unsigned u = __float_as_uint(smk[p]);
                if ((u & himask) == pref)
                    atomicAdd(&hist[(u >> shift) & 255], 1);
            }
            __syncthreads();
            if (tid == 0) {
                int rem = sh_rem;
                int cum = 0, bin = 255;
                for (; bin > 0; bin--) {
                    cum += hist[bin];
                    if (cum >= rem) break;
                }
                if (cum < rem) cum += hist[0];
                sh_rem = rem - (cum - hist[bin]);
                sh_prefix = pref | ((unsigned)bin << shift);
            }
            __syncthreads();
        }
        unsigned tb = sh_prefix;
        int quota = sh_rem;

        float sgt = 0.f, seq = 0.f; int ceq = 0;
        for (int p = tid; p < P_; p += 512) {
            float v = smk[p];
            unsigned u = __float_as_uint(v);
            if (u > tb) sgt += v;
            else if (u == tb) { seq += v; ceq++; }
        }
        float sgt_t = bRedF512(sgt);
        float seq_t = bRedF512(seq);
        int   ceq_t = bRedI512(ceq);
        bool ordered = (ceq_t != quota) && (tb != 0u);
        if (tid == 0) atomicAdd(&g_acc[1], (double)(sgt_t + (ordered ? 0.f : seq_t)));

        if (ordered) {
            int s0 = tid * SEG3, s1 = s0 + SEG3; if (s1 > P_) s1 = P_;
            int c = 0;
            for (int p = s0; p < s1; p++)
                if (__float_as_uint(smk[p]) == tb) c++;
            int pre = bScanEx512(c, sscan);
            float sord = 0.f; int r = pre;
            for (int p = s0; p < s1; p++) {
                if (__float_as_uint(smk[p]) == tb) {
                    if (r < quota) sord += smk[p];
                    r++;
                }
            }
            float st = bRedF512(sord);
            if (tid == 0) atomicAdd(&g_acc[1], (double)st);
        }
    } else {
        int b = blockIdx.x - 8;
        int np = g_numpos[b];
        int cap = np < MTT_ ? np : MTT_;
        if (tid == 0) g_selcnt[b] = cap;
        int s0 = tid * SEG3, s1 = s0 + SEG3; if (s1 > P_) s1 = P_;
        int c = 0;
        for (int p = s0; p < s1; p++)
            if (g_conf[b][p] > 0) c++;
        int pre = bScanEx512(c, sscan);
        int r = pre;
        for (int p = s0; p < s1; p++) {
            if (g_conf[b][p] > 0) {
                if (r < cap) g_sel[b][r] = p;
                r++;
            }
        }
        __syncthreads();
        for (int k = tid; k < cap; k += 512) {
            int p = g_sel[b][k];
            int o = g_pmi[b][p];
            const float* bg = box_gt + (size_t)(b * NOBJ_ + o) * 4;
            float bx1 = bg[0], by1 = bg[1], bx2 = bg[2], by2 = bg[3];
            float ax = bx1 * 138.f, bx = bx2 * 138.f;
            float x1 = fminf(ax, bx), x2 = fmaxf(ax, bx);
            x1 = fmaxf(x1 - 1.f, 0.f); x2 = fminf(x2 + 1.f, 138.f);
            float ay = by1 * 138.f, by = by2 * 138.f;
            float y1 = fminf(ay, by), y2 = fmaxf(ay, by);
            y1 = fmaxf(y1 - 1.f, 0.f); y2 = fminf(y2 + 1.f, 138.f);
            int xlo = (int)ceilf(x1), xhi = (int)ceilf(x2);
            int ylo = (int)ceilf(y1), yhi = (int)ceilf(y2);
            if (xlo < 0) xlo = 0; if (xhi > PW_) xhi = PW_;
            if (ylo < 0) ylo = 0; if (yhi > PH_) yhi = PH_;
            int4 r4; r4.x = xlo; r4.y = xhi; r4.z = ylo; r4.w = yhi;
            g_rect[b][k] = r4;
            double denom = (double)((bx2 - bx1) * (by2 - by1));
            g_invd[b][k] = (float)(1.0 / denom);
            g_obit[b][k] = o;
        }
    }
}

// ------------------------- K5: mask BCE, pixel-centric -------------------------
__global__ void __launch_bounds__(256) k_mask(const float* __restrict__ proto_p,
                                              const float* __restrict__ coef_p) {
    __shared__ float4 scoef[MTT_][8];
    __shared__ int4   srect[MTT_];
    __shared__ float  sinv[MTT_];
    __shared__ int    sob[MTT_];
    int b = blockIdx.y;
    int tid = threadIdx.x;
    int px = blockIdx.x * 256 + tid;
    int cnt = g_selcnt[b];

    for (int i = tid; i < cnt * 8; i += 256) {
        int k = i >> 3, q = i & 7;
        int p = g_sel[b][k];
        scoef[k][q] = ((const float4*)(coef_p + ((size_t)(b * P_ + p)) * KC_))[q];
    }
    for (int i = tid; i < cnt; i += 256) {
        srect[i] = g_rect[b][i];
        sinv[i]  = g_invd[b][i];
        sob[i]   = g_obit[b][i];
    }
    __syncthreads();

    float acc = 0.f;
    if (px < NPIX_ && cnt > 0) {
        int y = px / PW_, x = px % PW_;
        const float4* pp = (const float4*)(proto_p + (size_t)(b * NPIX_ + px) * KC_);
        float4 r0 = pp[0], r1 = pp[1], r2 = pp[2], r3 = pp[3];
        float4 r4 = pp[4], r5 = pp[5], r6 = pp[6], r7 = pp[7];
        unsigned dmb = g_dm[b][px];
        const float L = 16.118095651f;
        const float A  = -logf(1e-7f);
        const float Bc = -log1pf(-1e-7f);
        for (int k = 0; k < cnt; k++) {
            int4 r = srect[k];
            if (x >= r.x && x < r.y && y >= r.z && y < r.w) {
                const float4* ck = scoef[k];
                float4 c0 = ck[0], c1 = ck[1], c2 = ck[2], c3 = ck[3];
                float4 c4 = ck[4], c5 = ck[5], c6 = ck[6], c7 = ck[7];
                float z =
                    r0.x*c0.x + r0.y*c0.y + r0.z*c0.z + r0.w*c0.w +
                    r1.x*c1.x + r1.y*c1.y + r1.z*c1.z + r1.w*c1.w +
                    r2.x*c2.x + r2.y*c2.y + r2.z*c2.z + r2.w*c2.w +
                    r3.x*c3.x + r3.y*c3.y + r3.z*c3.z + r3.w*c3.w +
                    r4.x*c4.x + r4.y*c4.y + r4.z*c4.z + r4.w*c4.w +
                    r5.x*c5.x + r5.y*c5.y + r5.z*c5.z + r5.w*c5.w +
                    r6.x*c6.x + r6.y*c6.y + r6.z*c6.z + r6.w*c6.w +
                    r7.x*c7.x + r7.y*c7.y + r7.z*c7.z + r7.w*c7.w;
                float zc = fminf(fmaxf(z, -L), L);
                float sp = fmaxf(zc, 0.f) + __logf(1.f + __expf(-fabsf(zc)));
                int gt = (dmb >> sob[k]) & 1;
                float vp = sp - (gt ? (zc + A) : Bc);
                acc += vp * sinv[k];
            }
        }
    }
    float t = bRedF256(acc);
    if (tid == 0) atomicAdd(&g_mlsum[b], (double)t);
}

// ------------------------- K6: final combine -------------------------
__global__ void __launch_bounds__(256) k_final(float* out) {
    __shared__ double sd[8];
    int tid = threadIdx.x;
    const float A  = -logf(1e-7f);
    const float Bc = -log1pf(-1e-7f);
    double acc = 0.0;
    for (int i = tid; i < B_ * MTT_; i += 256) {
        int b = i / MTT_, k = i % MTT_;
        if (k < g_selcnt[b]) {
            int o = g_obit[b][k];
            int ones = g_ones[b][o];
            double c = (double)ones * (double)A + (double)(NPIX_ - ones) * (double)Bc;
            int np = g_numpos[b];
            double s = 1.0;
            if (np > MTT_) {
                float npf = (float)np;
                s = (double)(npf / fmaxf(fminf(npf, (float)MTT_), 1.f));
            }
            acc += c * (double)g_invd[b][k] * s;
        }
    }
    if (tid < B_) {
        int np = g_numpos[tid];
        double s = 1.0;
        if (np > MTT_) {
            float npf = (float)np;
            s = (double)(npf / fmaxf(fminf(npf, (float)MTT_), 1.f));
        }
        acc += g_mlsum[tid] * s;
    }
    int ln = tid & 31, wd = tid >> 5;
    #pragma unroll
    for (int o = 16; o; o >>= 1) acc += __shfl_down_sync(0xffffffffu, acc, o);
    if (ln == 0) sd[wd] = acc;
    __syncthreads();
    if (tid < 8) {
        acc = sd[tid];
        #pragma unroll
        for (int o = 4; o; o >>= 1) acc += __shfl_down_sync(0xffffffffu, acc, o);
        if (tid == 0) {
            double total = 1.5 * g_acc[0] + g_acc[1] + acc * 6.125 / 138.0 / 138.0;
            out[0] = (float)total;
        }
    }
}

// ------------------------- launch: 7-node linear chain -------------------------
extern "C" void kernel_launch(void* const* d_in, const int* in_sizes, int n_in,
                              void* d_out, int out_size) {
    const float* class_p  = (const float*)d_in[0];
    const float* box_p    = (const float*)d_in[1];
    const float* coef_p   = (const float*)d_in[2];
    const float* proto_p  = (const float*)d_in[3];
    const float* priors   = (const float*)d_in[4];
    const float* box_gt   = (const float*)d_in[5];
    const float* mask_gt  = (const float*)d_in[6];
    const int*   class_gt = (const int*)d_in[7];
    float* out = (float*)d_out;

    static bool inited = false;
    if (!inited) {
        cudaFuncSetAttribute(k_selpick, cudaFuncAttributeMaxDynamicSharedMemorySize, P_ * 4);
        inited = true;
    }

    k_init<<<1, 256>>>();
    k_big<<<BIG_BLOCKS, 256>>>(mask_gt, priors, box_gt, class_gt, class_p);
    k_override<<<1, 32>>>(class_gt);
    dim3 gm(MBLK, B_);
    k_posloss<<<gm, 256>>>(class_p, box_p, priors, box_gt);
    k_selpick<<<16, 512, P_ * 4>>>(box_gt);
    dim3 gk((NPIX_ + 255) / 256, B_);
    k_mask<<<gk, 256>>>(proto_p, coef_p);
    k_final<<<1, 256>>>(out);
}